// round 5
// baseline (speedup 1.0000x reference)
#include <cuda_runtime.h>
#include <cuda_bf16.h>
#include <cstdint>

// Problem constants
constexpr int Bb   = 6;
constexpr int T    = 1024;
constexpr int DIN  = 256;
constexpr int DOUT = 512;
constexpr int G    = 8;
constexpr int KSP  = DIN * G;   // 2048

// ---------------------------------------------------------------------------
// Device scratch
// ---------------------------------------------------------------------------
__device__ __align__(16) float          g_xn2[T * DIN];           // LN'd batch 2 (dog)
__device__ __align__(16) __nv_bfloat16  g_silu_hi[T * DIN];
__device__ __align__(16) __nv_bfloat16  g_silu_lo[T * DIN];
__device__ __align__(16) __nv_bfloat16  g_basis_hi[4ull * T * KSP];
__device__ __align__(16) __nv_bfloat16  g_basis_lo[4ull * T * KSP];
__device__ __align__(16) __nv_bfloat16  g_sw_hi[DOUT * KSP];
__device__ __align__(16) __nv_bfloat16  g_sw_lo[DOUT * KSP];
__device__ __align__(16) __nv_bfloat16  g_bw_hi[DOUT * DIN];
__device__ __align__(16) __nv_bfloat16  g_bw_lo[DOUT * DIN];

// ---------------------------------------------------------------------------
// Helpers
// ---------------------------------------------------------------------------
__device__ __forceinline__ void bsplit(float x, __nv_bfloat16& h, __nv_bfloat16& l)
{
    __nv_bfloat16 hb = __float2bfloat16(x);
    h = hb;
    l = __float2bfloat16(x - __bfloat162float(hb));
}

__device__ __forceinline__ uint32_t pack2(__nv_bfloat16 a, __nv_bfloat16 b)
{
    __nv_bfloat162 p = __halves2bfloat162(a, b);
    return *reinterpret_cast<uint32_t*>(&p);
}

__device__ __forceinline__ uint32_t smem_u32(const void* p)
{
    uint32_t a;
    asm("{ .reg .u64 t; cvta.to.shared.u64 t, %1; cvt.u32.u64 %0, t; }" : "=r"(a) : "l"(p));
    return a;
}

__device__ __forceinline__ void cpa(uint32_t d, const void* s)
{
    asm volatile("cp.async.cg.shared.global [%0], [%1], 16;" :: "r"(d), "l"(s));
}
#define CP_COMMIT() asm volatile("cp.async.commit_group;" ::: "memory")
#define CP_WAIT2()  asm volatile("cp.async.wait_group 2;"  ::: "memory")

#define LDSM_X4(R0,R1,R2,R3,ADDR) \
    asm volatile("ldmatrix.sync.aligned.m8n8.x4.shared.b16 {%0,%1,%2,%3}, [%4];" \
        : "=r"(R0), "=r"(R1), "=r"(R2), "=r"(R3) : "r"(ADDR))

__device__ __forceinline__ void mma16816(float* c, const uint32_t* a, const uint32_t* b)
{
    asm volatile(
        "mma.sync.aligned.m16n8k16.row.col.f32.bf16.bf16.f32 "
        "{%0,%1,%2,%3}, {%4,%5,%6,%7}, {%8,%9}, {%0,%1,%2,%3};"
        : "+f"(c[0]), "+f"(c[1]), "+f"(c[2]), "+f"(c[3])
        : "r"(a[0]), "r"(a[1]), "r"(a[2]), "r"(a[3]), "r"(b[0]), "r"(b[1]));
}

// ---------------------------------------------------------------------------
// Kernel 1: fused prep (unchanged from R4).
// ---------------------------------------------------------------------------
constexpr int LN_BLOCKS = Bb * T;                                   // 6144
constexpr int WS_ELEMS  = DOUT * KSP + DOUT * DIN;                  // 1179648
constexpr int WS_BLOCKS = WS_ELEMS / 256;                           // 4608

__global__ void prep_kernel(const float* __restrict__ X,
                            const float* __restrict__ w,
                            const float* __restrict__ bias,
                            const float* __restrict__ spline_w,
                            const float* __restrict__ base_w,
                            const float* __restrict__ grid_rbf,
                            const float* __restrict__ grid_bs)
{
    int bid = blockIdx.x;
    int tid = threadIdx.x;

    if (bid >= LN_BLOCKS) {
        int idx = (bid - LN_BLOCKS) * 256 + tid;
        const int NSP = DOUT * KSP;
        __nv_bfloat16 h, l;
        if (idx < NSP) {
            bsplit(spline_w[idx], h, l);
            g_sw_hi[idx] = h; g_sw_lo[idx] = l;
        } else {
            int j = idx - NSP;
            bsplit(base_w[j], h, l);
            g_bw_hi[j] = h; g_bw_lo[j] = l;
        }
        return;
    }

    int row = bid;
    int bb  = row >> 10;
    int t   = row & 1023;
    int i   = tid;
    float x = X[(size_t)row * DIN + i];

    float s = x, s2 = x * x;
    #pragma unroll
    for (int off = 16; off; off >>= 1) {
        s  += __shfl_xor_sync(0xffffffffu, s,  off);
        s2 += __shfl_xor_sync(0xffffffffu, s2, off);
    }
    __shared__ float ws[8], ws2[8];
    __shared__ float smu, srv;
    int wid = i >> 5, lid = i & 31;
    if (lid == 0) { ws[wid] = s; ws2[wid] = s2; }
    __syncthreads();
    if (i == 0) {
        float ts = 0.f, ts2 = 0.f;
        #pragma unroll
        for (int k = 0; k < 8; k++) { ts += ws[k]; ts2 += ws2[k]; }
        float mu  = ts * (1.f / DIN);
        float var = ts2 * (1.f / DIN) - mu * mu;
        smu = mu;
        srv = rsqrtf(var + 1e-5f);
    }
    __syncthreads();

    float xn = (x - smu) * srv * w[i] + bias[i];

    if (bb == 2) {
        g_xn2[(size_t)t * DIN + i] = xn;
        return;
    }
    if (bb == 3) {
        float sig = 1.f / (1.f + __expf(-xn));
        float v = xn * sig;
        __nv_bfloat16 h, l;
        bsplit(v, h, l);
        g_silu_hi[(size_t)t * DIN + i] = h;
        g_silu_lo[(size_t)t * DIN + i] = l;
        return;
    }

    int slot = (bb == 0) ? 0 : (bb == 1) ? 1 : (bb == 4) ? 2 : 3;
    __nv_bfloat16 h[G], l[G];

    if (bb == 0 || bb == 4) {
        const float invd = 7.f / 3.f;
        const float c    = -1.4426950408889634f;
        #pragma unroll
        for (int g = 0; g < G; g++) {
            float d = (xn - __ldg(&grid_rbf[g])) * invd;
            bsplit(exp2f(d * d * c), h[g], l[g]);
        }
    } else {
        float g[12];
        #pragma unroll
        for (int j = 0; j < 12; j++) g[j] = __ldg(&grid_bs[j]);
        float r1 = __fdividef(1.f, g[1] - g[0]);
        float r2 = __fdividef(1.f, g[2] - g[0]);
        float r3 = __fdividef(1.f, g[3] - g[0]);

        float bsv[11];
        #pragma unroll
        for (int j = 0; j < 11; j++)
            bsv[j] = (xn >= g[j] && xn < g[j + 1]) ? 1.f : 0.f;

        #pragma unroll
        for (int j = 0; j <= 9; j++)
            bsv[j] = (xn - g[j]) * r1 * bsv[j] + (g[j + 2] - xn) * r1 * bsv[j + 1];
        #pragma unroll
        for (int j = 0; j <= 8; j++)
            bsv[j] = (xn - g[j]) * r2 * bsv[j] + (g[j + 3] - xn) * r2 * bsv[j + 1];
        #pragma unroll
        for (int j = 0; j <= 7; j++)
            bsv[j] = (xn - g[j]) * r3 * bsv[j] + (g[j + 4] - xn) * r3 * bsv[j + 1];

        #pragma unroll
        for (int j = 0; j < 8; j++) bsplit(bsv[j], h[j], l[j]);
    }

    size_t off = (size_t)slot * T * KSP + (size_t)t * KSP + i * 8;
    uint4 uh = make_uint4(pack2(h[0],h[1]), pack2(h[2],h[3]), pack2(h[4],h[5]), pack2(h[6],h[7]));
    uint4 ul = make_uint4(pack2(l[0],l[1]), pack2(l[2],l[3]), pack2(l[4],l[5]), pack2(l[6],l[7]));
    *reinterpret_cast<uint4*>(g_basis_hi + off) = uh;
    *reinterpret_cast<uint4*>(g_basis_lo + off) = ul;
}

// ---------------------------------------------------------------------------
// Fat kernel: 128x128 gemm tiles (3-stage cp.async) + dog tiles, interleaved
// 5:16 over a period of 21 bids.
// ---------------------------------------------------------------------------
constexpr int BM = 128, BN = 128, BK = 32;
constexpr int OFF_AH = 0, OFF_AL = 8192, OFF_WH = 16384, OFF_WL = 24576;
constexpr int STAGE  = 32768;
constexpr int NSTAGE = 3;
constexpr int SMEM_BYTES = NSTAGE * STAGE;   // 96 KB dynamic

constexpr int GEMM_TILES = 160;   // 128 spline + 32 base
constexpr int DOG_TILES  = 512;
constexpr int FAT_BLOCKS = GEMM_TILES + DOG_TILES;   // 672 = 21 * 32

__device__ __forceinline__ uint32_t swz(uint32_t row, uint32_t slot)
{
    return row * 64u + (((slot ^ ((row >> 1) & 3u)) & 3u) << 4);
}

__device__ __forceinline__ void gemm_path(int gidx, char* smem, float* __restrict__ out)
{
    uint32_t sbase = smem_u32(smem);
    int tid = threadIdx.x;

    int z, tt;
    if (gidx < 128) { z = gidx >> 5; tt = gidx & 31; }
    else            { z = 4;         tt = gidx - 128; }
    int mt = tt >> 2, nt = tt & 3;
    int bb = (z == 0) ? 0 : (z == 1) ? 1 : (z == 2) ? 4 : (z == 3) ? 5 : 3;

    const __nv_bfloat16 *Ah, *Al, *Wh, *Wl;
    int K;
    if (z < 4) {
        Ah = g_basis_hi + (size_t)z * T * KSP;
        Al = g_basis_lo + (size_t)z * T * KSP;
        Wh = g_sw_hi; Wl = g_sw_lo; K = KSP;
    } else {
        Ah = g_silu_hi; Al = g_silu_lo;
        Wh = g_bw_hi;  Wl = g_bw_lo;  K = DIN;
    }
    int m0 = mt * BM, n0 = nt * BN;
    int nc = K / BK;

    // loader: 256 threads, 64 rows x 4 slots; each tile is 128 rows -> 2 cpa/tile
    int lrow = tid >> 2, lslot = tid & 3;
    size_t rowK = (size_t)64 * K;
    const __nv_bfloat16* pAh = Ah + (size_t)(m0 + lrow) * K + lslot * 8;
    const __nv_bfloat16* pAl = Al + (size_t)(m0 + lrow) * K + lslot * 8;
    const __nv_bfloat16* pWh = Wh + (size_t)(n0 + lrow) * K + lslot * 8;
    const __nv_bfloat16* pWl = Wl + (size_t)(n0 + lrow) * K + lslot * 8;
    uint32_t s0 = swz(lrow, lslot);
    uint32_t s1 = swz(lrow + 64, lslot);

    // compute: 8 warps = 2 (m) x 4 (n); warp tile 64 x 32
    int lane = tid & 31, wid = tid >> 5;
    int wm = wid >> 2, wn = wid & 3;
    uint32_t lr  = lane & 15;
    uint32_t lks = lane >> 4;

    float acc[4][4][4];
    #pragma unroll
    for (int a = 0; a < 4; a++)
        #pragma unroll
        for (int b = 0; b < 4; b++)
            #pragma unroll
            for (int cc = 0; cc < 4; cc++) acc[a][b][cc] = 0.f;

    // prologue: stages 0,1
    #pragma unroll
    for (int p = 0; p < 2; p++) {
        if (p < nc) {
            uint32_t sb = sbase + p * STAGE;
            int kc = p * BK;
            cpa(sb + OFF_AH + s0, pAh + kc);
            cpa(sb + OFF_AH + s1, pAh + rowK + kc);
            cpa(sb + OFF_AL + s0, pAl + kc);
            cpa(sb + OFF_AL + s1, pAl + rowK + kc);
            cpa(sb + OFF_WH + s0, pWh + kc);
            cpa(sb + OFF_WH + s1, pWh + rowK + kc);
            cpa(sb + OFF_WL + s0, pWl + kc);
            cpa(sb + OFF_WL + s1, pWl + rowK + kc);
        }
        CP_COMMIT();
    }

    int st = 0;   // stage of chunk c
    for (int c = 0; c < nc; c++) {
        // issue load for chunk c+2
        int cp2 = c + 2;
        if (cp2 < nc) {
            int stn = (st + 2 >= NSTAGE) ? st + 2 - NSTAGE : st + 2;
            uint32_t sb = sbase + stn * STAGE;
            int kc = cp2 * BK;
            cpa(sb + OFF_AH + s0, pAh + kc);
            cpa(sb + OFF_AH + s1, pAh + rowK + kc);
            cpa(sb + OFF_AL + s0, pAl + kc);
            cpa(sb + OFF_AL + s1, pAl + rowK + kc);
            cpa(sb + OFF_WH + s0, pWh + kc);
            cpa(sb + OFF_WH + s1, pWh + rowK + kc);
            cpa(sb + OFF_WL + s0, pWl + kc);
            cpa(sb + OFF_WL + s1, pWl + rowK + kc);
        }
        CP_COMMIT();
        CP_WAIT2();            // chunk c's group is complete
        __syncthreads();

        uint32_t sb = sbase + st * STAGE;
        #pragma unroll
        for (int ks = 0; ks < 2; ks++) {
            uint32_t slot = 2 * ks + lks;
            uint32_t aF[4][4], bH[4][2], bL[4][2];

            // A-hi fragments: 4 m-subtiles of 16 rows
            #pragma unroll
            for (int mi = 0; mi < 4; mi++) {
                uint32_t ad = sb + OFF_AH + swz(wm * 64 + mi * 16 + lr, slot);
                LDSM_X4(aF[mi][0], aF[mi][1], aF[mi][2], aF[mi][3], ad);
            }
            // W-hi fragments: 32 cols
            #pragma unroll
            for (int p = 0; p < 2; p++) {
                uint32_t t0, t1, t2, t3;
                uint32_t ad = sb + OFF_WH + swz(wn * 32 + p * 16 + lr, slot);
                LDSM_X4(t0, t1, t2, t3, ad);
                bH[2*p][0] = t0; bH[2*p][1] = t2;
                bH[2*p+1][0] = t1; bH[2*p+1][1] = t3;
            }
            // term 1: Ah * Wh
            #pragma unroll
            for (int mi = 0; mi < 4; mi++)
                #pragma unroll
                for (int ni = 0; ni < 4; ni++)
                    mma16816(acc[mi][ni], aF[mi], bH[ni]);

            // W-lo fragments
            #pragma unroll
            for (int p = 0; p < 2; p++) {
                uint32_t t0, t1, t2, t3;
                uint32_t ad = sb + OFF_WL + swz(wn * 32 + p * 16 + lr, slot);
                LDSM_X4(t0, t1, t2, t3, ad);
                bL[2*p][0] = t0; bL[2*p][1] = t2;
                bL[2*p+1][0] = t1; bL[2*p+1][1] = t3;
            }
            // term 2: Ah * Wl
            #pragma unroll
            for (int mi = 0; mi < 4; mi++)
                #pragma unroll
                for (int ni = 0; ni < 4; ni++)
                    mma16816(acc[mi][ni], aF[mi], bL[ni]);

            // A-lo fragments (reuse regs)
            #pragma unroll
            for (int mi = 0; mi < 4; mi++) {
                uint32_t ad = sb + OFF_AL + swz(wm * 64 + mi * 16 + lr, slot);
                LDSM_X4(aF[mi][0], aF[mi][1], aF[mi][2], aF[mi][3], ad);
            }
            // term 3: Al * Wh
            #pragma unroll
            for (int mi = 0; mi < 4; mi++)
                #pragma unroll
                for (int ni = 0; ni < 4; ni++)
                    mma16816(acc[mi][ni], aF[mi], bH[ni]);
        }
        __syncthreads();
        st = (st + 1 == NSTAGE) ? 0 : st + 1;
    }

    float* Cb = out + (size_t)bb * T * DOUT;
    int rbase = m0 + wm * 64 + (lane >> 2);
    int cbase = n0 + wn * 32 + (lane & 3) * 2;
    #pragma unroll
    for (int mi = 0; mi < 4; mi++) {
        #pragma unroll
        for (int ni = 0; ni < 4; ni++) {
            int r = rbase + mi * 16;
            int cc = cbase + ni * 8;
            *reinterpret_cast<float2*>(&Cb[(size_t)r * DOUT + cc]) =
                make_float2(acc[mi][ni][0], acc[mi][ni][1]);
            *reinterpret_cast<float2*>(&Cb[(size_t)(r + 8) * DOUT + cc]) =
                make_float2(acc[mi][ni][2], acc[mi][ni][3]);
        }
    }
}

struct DogS {
    float xn[32][33];
    float rs[32][33];
    float trrs[32][33];
    float nbw[32][33];
};

__device__ __forceinline__ void dog_path(int didx, char* smem,
                                         const float* __restrict__ base_w,
                                         const float* __restrict__ scale,
                                         const float* __restrict__ trans,
                                         float* __restrict__ out)
{
    DogS& S = *reinterpret_cast<DogS*>(smem);
    int o0 = (didx & 15) * 32;
    int t0 = (didx >> 4) * 32;
    int tid = threadIdx.x;
    int tx = tid & 31, ty = tid >> 5;

    float acc[4] = {0.f, 0.f, 0.f, 0.f};
    const float C = -0.7213475204444817f;   // -0.5*log2(e)

    for (int ic = 0; ic < DIN; ic += 32) {
        #pragma unroll
        for (int p = 0; p < 4; p++) {
            int idx = tid + p * 256;
            int r = idx >> 5, c = idx & 31;
            S.xn[r][c] = g_xn2[(size_t)(t0 + r) * DIN + ic + c];
            size_t oi = (size_t)(o0 + r) * DIN + ic + c;
            float rs = __fdividef(1.f, scale[oi]);
            S.rs[r][c]   = rs;
            S.trrs[r][c] = trans[oi] * rs;
            S.nbw[r][c]  = -base_w[oi];
        }
        __syncthreads();

        #pragma unroll
        for (int i = 0; i < 32; i++) {
            float trrs = S.trrs[tx][i], rsv = S.rs[tx][i], nbw = S.nbw[tx][i];
            #pragma unroll
            for (int j = 0; j < 4; j++) {
                float x = S.xn[ty * 4 + j][i];
                float u = fmaf(x, rsv, -trrs);
                float e = exp2f((u * C) * u);
                acc[j] = fmaf(u * e, nbw, acc[j]);
            }
        }
        __syncthreads();
    }

    #pragma unroll
    for (int j = 0; j < 4; j++)
        out[(size_t)(2 * T + t0 + ty * 4 + j) * DOUT + o0 + tx] = acc[j];
}

__global__ void __launch_bounds__(256, 2)
fat_kernel(float* __restrict__ out,
           const float* __restrict__ base_w,
           const float* __restrict__ scale,
           const float* __restrict__ trans)
{
    extern __shared__ __align__(16) char smem[];
    int bid = blockIdx.x;
    int grp = bid / 21, rem = bid % 21;    // 672 = 21 * 32; 5 gemm + 16 dog
    if (rem < 5) gemm_path(grp * 5 + rem, smem, out);
    else         dog_path(grp * 16 + (rem - 5), smem, base_w, scale, trans, out);
}

// ---------------------------------------------------------------------------
extern "C" void kernel_launch(void* const* d_in, const int* in_sizes, int n_in,
                              void* d_out, int out_size)
{
    const float* X        = (const float*)d_in[0];
    const float* ln_w     = (const float*)d_in[1];
    const float* ln_b     = (const float*)d_in[2];
    const float* base_w   = (const float*)d_in[3];
    const float* spline_w = (const float*)d_in[4];
    const float* scale    = (const float*)d_in[5];
    const float* trans    = (const float*)d_in[6];
    const float* grid_rbf = (const float*)d_in[7];
    const float* grid_bs  = (const float*)d_in[8];
    float* out = (float*)d_out;

    cudaFuncSetAttribute(fat_kernel, cudaFuncAttributeMaxDynamicSharedMemorySize, SMEM_BYTES);

    prep_kernel<<<LN_BLOCKS + WS_BLOCKS, 256>>>(X, ln_w, ln_b, spline_w, base_w,
                                                grid_rbf, grid_bs);
    fat_kernel<<<FAT_BLOCKS, 256, SMEM_BYTES>>>(out, base_w, scale, trans);
}

// round 6
// speedup vs baseline: 1.2425x; 1.2425x over previous
#include <cuda_runtime.h>
#include <cuda_bf16.h>
#include <cstdint>

// Problem constants
constexpr int Bb   = 6;
constexpr int T    = 1024;
constexpr int DIN  = 256;
constexpr int DOUT = 512;
constexpr int G    = 8;
constexpr int KSP  = DIN * G;   // 2048

// ---------------------------------------------------------------------------
// Device scratch
// ---------------------------------------------------------------------------
__device__ __align__(16) float          g_xn2[T * DIN];           // LN'd batch 2 (dog)
__device__ __align__(16) __nv_bfloat16  g_silu_hi[T * DIN];
__device__ __align__(16) __nv_bfloat16  g_silu_lo[T * DIN];
__device__ __align__(16) __nv_bfloat16  g_basis_hi[4ull * T * KSP];
__device__ __align__(16) __nv_bfloat16  g_basis_lo[4ull * T * KSP];
__device__ __align__(16) __nv_bfloat16  g_sw_hi[DOUT * KSP];
__device__ __align__(16) __nv_bfloat16  g_sw_lo[DOUT * KSP];
__device__ __align__(16) __nv_bfloat16  g_bw_hi[DOUT * DIN];
__device__ __align__(16) __nv_bfloat16  g_bw_lo[DOUT * DIN];

// ---------------------------------------------------------------------------
// Helpers
// ---------------------------------------------------------------------------
__device__ __forceinline__ void bsplit(float x, __nv_bfloat16& h, __nv_bfloat16& l)
{
    __nv_bfloat16 hb = __float2bfloat16(x);
    h = hb;
    l = __float2bfloat16(x - __bfloat162float(hb));
}

__device__ __forceinline__ uint32_t pack2(__nv_bfloat16 a, __nv_bfloat16 b)
{
    __nv_bfloat162 p = __halves2bfloat162(a, b);
    return *reinterpret_cast<uint32_t*>(&p);
}

__device__ __forceinline__ uint32_t smem_u32(const void* p)
{
    uint32_t a;
    asm("{ .reg .u64 t; cvta.to.shared.u64 t, %1; cvt.u32.u64 %0, t; }" : "=r"(a) : "l"(p));
    return a;
}

__device__ __forceinline__ void cpa(uint32_t d, const void* s)
{
    asm volatile("cp.async.cg.shared.global [%0], [%1], 16;" :: "r"(d), "l"(s));
}
#define CP_COMMIT() asm volatile("cp.async.commit_group;" ::: "memory")
#define CP_WAIT1()  asm volatile("cp.async.wait_group 1;"  ::: "memory")

#define LDSM_X4(R0,R1,R2,R3,ADDR) \
    asm volatile("ldmatrix.sync.aligned.m8n8.x4.shared.b16 {%0,%1,%2,%3}, [%4];" \
        : "=r"(R0), "=r"(R1), "=r"(R2), "=r"(R3) : "r"(ADDR))

__device__ __forceinline__ void mma16816(float* c, const uint32_t* a, const uint32_t* b)
{
    asm volatile(
        "mma.sync.aligned.m16n8k16.row.col.f32.bf16.bf16.f32 "
        "{%0,%1,%2,%3}, {%4,%5,%6,%7}, {%8,%9}, {%0,%1,%2,%3};"
        : "+f"(c[0]), "+f"(c[1]), "+f"(c[2]), "+f"(c[3])
        : "r"(a[0]), "r"(a[1]), "r"(a[2]), "r"(a[3]), "r"(b[0]), "r"(b[1]));
}

// ---------------------------------------------------------------------------
// Kernel 1: fused prep (LN + basis/silu + weight split)
// ---------------------------------------------------------------------------
constexpr int LN_BLOCKS = Bb * T;                                   // 6144
constexpr int WS_ELEMS  = DOUT * KSP + DOUT * DIN;                  // 1179648
constexpr int WS_BLOCKS = WS_ELEMS / 256;                           // 4608

__global__ void prep_kernel(const float* __restrict__ X,
                            const float* __restrict__ w,
                            const float* __restrict__ bias,
                            const float* __restrict__ spline_w,
                            const float* __restrict__ base_w,
                            const float* __restrict__ grid_rbf,
                            const float* __restrict__ grid_bs)
{
    int bid = blockIdx.x;
    int tid = threadIdx.x;

    if (bid >= LN_BLOCKS) {
        int idx = (bid - LN_BLOCKS) * 256 + tid;
        const int NSP = DOUT * KSP;
        __nv_bfloat16 h, l;
        if (idx < NSP) {
            bsplit(spline_w[idx], h, l);
            g_sw_hi[idx] = h; g_sw_lo[idx] = l;
        } else {
            int j = idx - NSP;
            bsplit(base_w[j], h, l);
            g_bw_hi[j] = h; g_bw_lo[j] = l;
        }
        return;
    }

    int row = bid;
    int bb  = row >> 10;
    int t   = row & 1023;
    int i   = tid;
    float x = X[(size_t)row * DIN + i];

    float s = x, s2 = x * x;
    #pragma unroll
    for (int off = 16; off; off >>= 1) {
        s  += __shfl_xor_sync(0xffffffffu, s,  off);
        s2 += __shfl_xor_sync(0xffffffffu, s2, off);
    }
    __shared__ float ws[8], ws2[8];
    __shared__ float smu, srv;
    int wid = i >> 5, lid = i & 31;
    if (lid == 0) { ws[wid] = s; ws2[wid] = s2; }
    __syncthreads();
    if (i == 0) {
        float ts = 0.f, ts2 = 0.f;
        #pragma unroll
        for (int k = 0; k < 8; k++) { ts += ws[k]; ts2 += ws2[k]; }
        float mu  = ts * (1.f / DIN);
        float var = ts2 * (1.f / DIN) - mu * mu;
        smu = mu;
        srv = rsqrtf(var + 1e-5f);
    }
    __syncthreads();

    float xn = (x - smu) * srv * w[i] + bias[i];

    if (bb == 2) {
        g_xn2[(size_t)t * DIN + i] = xn;
        return;
    }
    if (bb == 3) {
        float sig = 1.f / (1.f + __expf(-xn));
        float v = xn * sig;
        __nv_bfloat16 h, l;
        bsplit(v, h, l);
        g_silu_hi[(size_t)t * DIN + i] = h;
        g_silu_lo[(size_t)t * DIN + i] = l;
        return;
    }

    int slot = (bb == 0) ? 0 : (bb == 1) ? 1 : (bb == 4) ? 2 : 3;
    __nv_bfloat16 h[G], l[G];

    if (bb == 0 || bb == 4) {
        const float invd = 7.f / 3.f;
        const float c    = -1.4426950408889634f;
        #pragma unroll
        for (int g = 0; g < G; g++) {
            float d = (xn - __ldg(&grid_rbf[g])) * invd;
            bsplit(exp2f(d * d * c), h[g], l[g]);
        }
    } else {
        float g[12];
        #pragma unroll
        for (int j = 0; j < 12; j++) g[j] = __ldg(&grid_bs[j]);
        float r1 = __fdividef(1.f, g[1] - g[0]);
        float r2 = __fdividef(1.f, g[2] - g[0]);
        float r3 = __fdividef(1.f, g[3] - g[0]);

        float bsv[11];
        #pragma unroll
        for (int j = 0; j < 11; j++)
            bsv[j] = (xn >= g[j] && xn < g[j + 1]) ? 1.f : 0.f;

        #pragma unroll
        for (int j = 0; j <= 9; j++)
            bsv[j] = (xn - g[j]) * r1 * bsv[j] + (g[j + 2] - xn) * r1 * bsv[j + 1];
        #pragma unroll
        for (int j = 0; j <= 8; j++)
            bsv[j] = (xn - g[j]) * r2 * bsv[j] + (g[j + 3] - xn) * r2 * bsv[j + 1];
        #pragma unroll
        for (int j = 0; j <= 7; j++)
            bsv[j] = (xn - g[j]) * r3 * bsv[j] + (g[j + 4] - xn) * r3 * bsv[j + 1];

        #pragma unroll
        for (int j = 0; j < 8; j++) bsplit(bsv[j], h[j], l[j]);
    }

    size_t off = (size_t)slot * T * KSP + (size_t)t * KSP + i * 8;
    uint4 uh = make_uint4(pack2(h[0],h[1]), pack2(h[2],h[3]), pack2(h[4],h[5]), pack2(h[6],h[7]));
    uint4 ul = make_uint4(pack2(l[0],l[1]), pack2(l[2],l[3]), pack2(l[4],l[5]), pack2(l[6],l[7]));
    *reinterpret_cast<uint4*>(g_basis_hi + off) = uh;
    *reinterpret_cast<uint4*>(g_basis_lo + off) = ul;
}

// ---------------------------------------------------------------------------
// Fat kernel: 64x128 gemm tiles (3-stage, 1 barrier/chunk) + dog tiles,
// interleaved 5:8 over a period of 13 bids. 72 KB dynamic smem, 3 CTA/SM.
// ---------------------------------------------------------------------------
constexpr int BM = 64, BN = 128, BK = 32;
constexpr int OFF_AH = 0, OFF_AL = 4096, OFF_WH = 8192, OFF_WL = 16384;
constexpr int STAGE  = 24576;
constexpr int NSTAGE = 3;
constexpr int SMEM_BYTES = NSTAGE * STAGE;   // 72 KB

constexpr int GEMM_TILES = 320;   // 256 spline + 64 base
constexpr int DOG_TILES  = 512;   // 16 o-tiles x 32 t-tiles
constexpr int FAT_BLOCKS = GEMM_TILES + DOG_TILES;   // 832 = 13 * 64

__device__ __forceinline__ uint32_t swz(uint32_t row, uint32_t slot)
{
    return row * 64u + (((slot ^ ((row >> 1) & 3u)) & 3u) << 4);
}

__device__ __forceinline__ void gemm_path(int gidx, char* smem, float* __restrict__ out)
{
    uint32_t sbase = smem_u32(smem);
    int tid = threadIdx.x;

    int z, tt;
    if (gidx < 256) { z = gidx >> 6; tt = gidx & 63; }
    else            { z = 4;         tt = gidx - 256; }
    int mt = tt >> 2, nt = tt & 3;
    int bb = (z == 0) ? 0 : (z == 1) ? 1 : (z == 2) ? 4 : (z == 3) ? 5 : 3;

    const __nv_bfloat16 *Ah, *Al, *Wh, *Wl;
    int K;
    if (z < 4) {
        Ah = g_basis_hi + (size_t)z * T * KSP;
        Al = g_basis_lo + (size_t)z * T * KSP;
        Wh = g_sw_hi; Wl = g_sw_lo; K = KSP;
    } else {
        Ah = g_silu_hi; Al = g_silu_lo;
        Wh = g_bw_hi;  Wl = g_bw_lo;  K = DIN;
    }
    int m0 = mt * BM, n0 = nt * BN;
    int nc = K / BK;

    int lrow = tid >> 2, lslot = tid & 3;
    const __nv_bfloat16* gAh  = Ah + (size_t)(m0 + lrow) * K + lslot * 8;
    const __nv_bfloat16* gAl  = Al + (size_t)(m0 + lrow) * K + lslot * 8;
    const __nv_bfloat16* gW0h = Wh + (size_t)(n0 + lrow) * K + lslot * 8;
    const __nv_bfloat16* gW1h = Wh + (size_t)(n0 + lrow + 64) * K + lslot * 8;
    const __nv_bfloat16* gW0l = Wl + (size_t)(n0 + lrow) * K + lslot * 8;
    const __nv_bfloat16* gW1l = Wl + (size_t)(n0 + lrow + 64) * K + lslot * 8;
    uint32_t sA  = swz(lrow, lslot);
    uint32_t sW0 = swz(lrow, lslot);
    uint32_t sW1 = swz(lrow + 64, lslot);

    int lane = tid & 31, wid = tid >> 5;
    int wm = wid >> 2, wn = wid & 3;          // warp tile 32x32
    uint32_t lr  = lane & 15;
    uint32_t lks = lane >> 4;

    float acc[2][4][4];
    #pragma unroll
    for (int a = 0; a < 2; a++)
        #pragma unroll
        for (int b = 0; b < 4; b++)
            #pragma unroll
            for (int cc = 0; cc < 4; cc++) acc[a][b][cc] = 0.f;

    // prologue: issue chunks 0,1 into stages 0,1
    #pragma unroll
    for (int p = 0; p < 2; p++) {
        if (p < nc) {
            uint32_t sb = sbase + p * STAGE;
            int kc = p * BK;
            cpa(sb + OFF_AH + sA,  gAh + kc);
            cpa(sb + OFF_AL + sA,  gAl + kc);
            cpa(sb + OFF_WH + sW0, gW0h + kc);
            cpa(sb + OFF_WH + sW1, gW1h + kc);
            cpa(sb + OFF_WL + sW0, gW0l + kc);
            cpa(sb + OFF_WL + sW1, gW1l + kc);
        }
        CP_COMMIT();
    }

    int st = 0;
    for (int c = 0; c < nc; c++) {
        CP_WAIT1();          // chunk c complete (c+1 may remain in flight)
        __syncthreads();     // single barrier per chunk

        // issue chunk c+2 into stage (st+2)%3 — safe: all warps finished compute(c-1)
        if (c + 2 < nc) {
            int stn = (st + 2 >= NSTAGE) ? st + 2 - NSTAGE : st + 2;
            uint32_t sb = sbase + stn * STAGE;
            int kc = (c + 2) * BK;
            cpa(sb + OFF_AH + sA,  gAh + kc);
            cpa(sb + OFF_AL + sA,  gAl + kc);
            cpa(sb + OFF_WH + sW0, gW0h + kc);
            cpa(sb + OFF_WH + sW1, gW1h + kc);
            cpa(sb + OFF_WL + sW0, gW0l + kc);
            cpa(sb + OFF_WL + sW1, gW1l + kc);
        }
        CP_COMMIT();

        uint32_t sb = sbase + st * STAGE;
        #pragma unroll
        for (int ks = 0; ks < 2; ks++) {
            uint32_t slot = 2 * ks + lks;
            uint32_t aF[2][4], bH[4][2], bL[4][2];

            #pragma unroll
            for (int mi = 0; mi < 2; mi++) {
                uint32_t ad = sb + OFF_AH + swz(wm * 32 + mi * 16 + lr, slot);
                LDSM_X4(aF[mi][0], aF[mi][1], aF[mi][2], aF[mi][3], ad);
            }
            #pragma unroll
            for (int p = 0; p < 2; p++) {
                uint32_t t0, t1, t2, t3;
                uint32_t ad = sb + OFF_WH + swz(wn * 32 + p * 16 + lr, slot);
                LDSM_X4(t0, t1, t2, t3, ad);
                bH[2*p][0] = t0; bH[2*p][1] = t2;
                bH[2*p+1][0] = t1; bH[2*p+1][1] = t3;
            }
            #pragma unroll
            for (int mi = 0; mi < 2; mi++)
                #pragma unroll
                for (int ni = 0; ni < 4; ni++)
                    mma16816(acc[mi][ni], aF[mi], bH[ni]);

            #pragma unroll
            for (int p = 0; p < 2; p++) {
                uint32_t t0, t1, t2, t3;
                uint32_t ad = sb + OFF_WL + swz(wn * 32 + p * 16 + lr, slot);
                LDSM_X4(t0, t1, t2, t3, ad);
                bL[2*p][0] = t0; bL[2*p][1] = t2;
                bL[2*p+1][0] = t1; bL[2*p+1][1] = t3;
            }
            #pragma unroll
            for (int mi = 0; mi < 2; mi++)
                #pragma unroll
                for (int ni = 0; ni < 4; ni++)
                    mma16816(acc[mi][ni], aF[mi], bL[ni]);

            #pragma unroll
            for (int mi = 0; mi < 2; mi++) {
                uint32_t ad = sb + OFF_AL + swz(wm * 32 + mi * 16 + lr, slot);
                LDSM_X4(aF[mi][0], aF[mi][1], aF[mi][2], aF[mi][3], ad);
            }
            #pragma unroll
            for (int mi = 0; mi < 2; mi++)
                #pragma unroll
                for (int ni = 0; ni < 4; ni++)
                    mma16816(acc[mi][ni], aF[mi], bH[ni]);
        }
        st = (st + 1 == NSTAGE) ? 0 : st + 1;
    }

    float* Cb = out + (size_t)bb * T * DOUT;
    int rbase = m0 + wm * 32 + (lane >> 2);
    int cbase = n0 + wn * 32 + (lane & 3) * 2;
    #pragma unroll
    for (int mi = 0; mi < 2; mi++) {
        #pragma unroll
        for (int ni = 0; ni < 4; ni++) {
            int r = rbase + mi * 16;
            int cc = cbase + ni * 8;
            *reinterpret_cast<float2*>(&Cb[(size_t)r * DOUT + cc]) =
                make_float2(acc[mi][ni][0], acc[mi][ni][1]);
            *reinterpret_cast<float2*>(&Cb[(size_t)(r + 8) * DOUT + cc]) =
                make_float2(acc[mi][ni][2], acc[mi][ni][3]);
        }
    }
}

struct DogS {
    float xn[32][33];
    float rs[32][33];
    float trrs[32][33];
    float nbw[32][33];
};

__device__ __forceinline__ void dog_path(int didx, char* smem,
                                         const float* __restrict__ base_w,
                                         const float* __restrict__ scale,
                                         const float* __restrict__ trans,
                                         float* __restrict__ out)
{
    DogS* S = reinterpret_cast<DogS*>(smem);   // double buffer: S[0], S[1]
    int o0 = (didx & 15) * 32;
    int t0 = (didx >> 4) * 32;
    int tid = threadIdx.x;
    int tx = tid & 31, ty = tid >> 5;
    int r4 = tid >> 5, c4 = tid & 31;          // per-p row/col base

    float acc[4] = {0.f, 0.f, 0.f, 0.f};
    const float C = -0.7213475204444817f;      // -0.5*log2(e)

    float pxn[4], prs[4], ptr[4], pbw[4];

    // prologue: load + store chunk 0
    #pragma unroll
    for (int p = 0; p < 4; p++) {
        int r = r4 + p * 8;
        pxn[p] = g_xn2[(size_t)(t0 + r) * DIN + c4];
        size_t oi = (size_t)(o0 + r) * DIN + c4;
        prs[p] = __fdividef(1.f, scale[oi]);
        ptr[p] = trans[oi];
        pbw[p] = base_w[oi];
    }
    #pragma unroll
    for (int p = 0; p < 4; p++) {
        int r = r4 + p * 8;
        S[0].xn[r][c4]   = pxn[p];
        S[0].rs[r][c4]   = prs[p];
        S[0].trrs[r][c4] = ptr[p] * prs[p];
        S[0].nbw[r][c4]  = -pbw[p];
    }

    for (int cc = 0; cc < DIN / 32; cc++) {
        __syncthreads();
        // prefetch chunk cc+1 into registers (overlaps compute below)
        if (cc + 1 < DIN / 32) {
            int ic = (cc + 1) * 32;
            #pragma unroll
            for (int p = 0; p < 4; p++) {
                int r = r4 + p * 8;
                pxn[p] = g_xn2[(size_t)(t0 + r) * DIN + ic + c4];
                size_t oi = (size_t)(o0 + r) * DIN + ic + c4;
                prs[p] = __fdividef(1.f, scale[oi]);
                ptr[p] = trans[oi];
                pbw[p] = base_w[oi];
            }
        }

        DogS& B = S[cc & 1];
        #pragma unroll
        for (int i = 0; i < 32; i++) {
            float trrs = B.trrs[tx][i], rsv = B.rs[tx][i], nbw = B.nbw[tx][i];
            #pragma unroll
            for (int j = 0; j < 4; j++) {
                float x = B.xn[ty * 4 + j][i];
                float u = fmaf(x, rsv, -trrs);
                float e = exp2f((u * C) * u);
                acc[j] = fmaf(u * e, nbw, acc[j]);
            }
        }

        if (cc + 1 < DIN / 32) {
            DogS& Bn = S[(cc + 1) & 1];
            #pragma unroll
            for (int p = 0; p < 4; p++) {
                int r = r4 + p * 8;
                Bn.xn[r][c4]   = pxn[p];
                Bn.rs[r][c4]   = prs[p];
                Bn.trrs[r][c4] = ptr[p] * prs[p];
                Bn.nbw[r][c4]  = -pbw[p];
            }
        }
    }

    #pragma unroll
    for (int j = 0; j < 4; j++)
        out[(size_t)(2 * T + t0 + ty * 4 + j) * DOUT + o0 + tx] = acc[j];
}

__global__ void __launch_bounds__(256, 3)
fat_kernel(float* __restrict__ out,
           const float* __restrict__ base_w,
           const float* __restrict__ scale,
           const float* __restrict__ trans)
{
    extern __shared__ __align__(16) char smem[];
    int bid = blockIdx.x;
    int grp = bid / 13, rem = bid % 13;    // 832 = 13 * 64; 5 gemm + 8 dog
    if (rem < 5) gemm_path(grp * 5 + rem, smem, out);
    else         dog_path(grp * 8 + (rem - 5), smem, base_w, scale, trans, out);
}

// ---------------------------------------------------------------------------
extern "C" void kernel_launch(void* const* d_in, const int* in_sizes, int n_in,
                              void* d_out, int out_size)
{
    const float* X        = (const float*)d_in[0];
    const float* ln_w     = (const float*)d_in[1];
    const float* ln_b     = (const float*)d_in[2];
    const float* base_w   = (const float*)d_in[3];
    const float* spline_w = (const float*)d_in[4];
    const float* scale    = (const float*)d_in[5];
    const float* trans    = (const float*)d_in[6];
    const float* grid_rbf = (const float*)d_in[7];
    const float* grid_bs  = (const float*)d_in[8];
    float* out = (float*)d_out;

    cudaFuncSetAttribute(fat_kernel, cudaFuncAttributeMaxDynamicSharedMemorySize, SMEM_BYTES);

    prep_kernel<<<LN_BLOCKS + WS_BLOCKS, 256>>>(X, ln_w, ln_b, spline_w, base_w,
                                                grid_rbf, grid_bs);
    fat_kernel<<<FAT_BLOCKS, 256, SMEM_BYTES>>>(out, base_w, scale, trans);
}

// round 7
// speedup vs baseline: 1.4142x; 1.1381x over previous
#include <cuda_runtime.h>
#include <cuda_bf16.h>
#include <cstdint>

// Problem constants
constexpr int Bb   = 6;
constexpr int T    = 1024;
constexpr int DIN  = 256;
constexpr int DOUT = 512;
constexpr int G    = 8;
constexpr int KSP  = DIN * G;   // 2048

// ---------------------------------------------------------------------------
// Device scratch
// ---------------------------------------------------------------------------
__device__ __align__(16) float          g_xn2[T * DIN];           // LN'd batch 2 (dog)
__device__ __align__(16) __nv_bfloat16  g_silu_hi[T * DIN];
__device__ __align__(16) __nv_bfloat16  g_silu_lo[T * DIN];
__device__ __align__(16) __nv_bfloat16  g_basis_hi[4ull * T * KSP];
__device__ __align__(16) __nv_bfloat16  g_basis_lo[4ull * T * KSP];
__device__ __align__(16) __nv_bfloat16  g_sw_hi[DOUT * KSP];
__device__ __align__(16) __nv_bfloat16  g_sw_lo[DOUT * KSP];
__device__ __align__(16) __nv_bfloat16  g_bw_hi[DOUT * DIN];
__device__ __align__(16) __nv_bfloat16  g_bw_lo[DOUT * DIN];

// ---------------------------------------------------------------------------
// Helpers
// ---------------------------------------------------------------------------
__device__ __forceinline__ void bsplit(float x, __nv_bfloat16& h, __nv_bfloat16& l)
{
    __nv_bfloat16 hb = __float2bfloat16(x);
    h = hb;
    l = __float2bfloat16(x - __bfloat162float(hb));
}

__device__ __forceinline__ uint32_t pack2(__nv_bfloat16 a, __nv_bfloat16 b)
{
    __nv_bfloat162 p = __halves2bfloat162(a, b);
    return *reinterpret_cast<uint32_t*>(&p);
}

__device__ __forceinline__ uint32_t smem_u32(const void* p)
{
    uint32_t a;
    asm("{ .reg .u64 t; cvta.to.shared.u64 t, %1; cvt.u32.u64 %0, t; }" : "=r"(a) : "l"(p));
    return a;
}

__device__ __forceinline__ void cpa(uint32_t d, const void* s)
{
    asm volatile("cp.async.cg.shared.global [%0], [%1], 16;" :: "r"(d), "l"(s));
}
#define CP_COMMIT() asm volatile("cp.async.commit_group;" ::: "memory")
#define CP_WAIT1()  asm volatile("cp.async.wait_group 1;"  ::: "memory")

#define LDSM_X4(R0,R1,R2,R3,ADDR) \
    asm volatile("ldmatrix.sync.aligned.m8n8.x4.shared.b16 {%0,%1,%2,%3}, [%4];" \
        : "=r"(R0), "=r"(R1), "=r"(R2), "=r"(R3) : "r"(ADDR))

__device__ __forceinline__ void mma16816(float* c, const uint32_t* a, const uint32_t* b)
{
    asm volatile(
        "mma.sync.aligned.m16n8k16.row.col.f32.bf16.bf16.f32 "
        "{%0,%1,%2,%3}, {%4,%5,%6,%7}, {%8,%9}, {%0,%1,%2,%3};"
        : "+f"(c[0]), "+f"(c[1]), "+f"(c[2]), "+f"(c[3])
        : "r"(a[0]), "r"(a[1]), "r"(a[2]), "r"(a[3]), "r"(b[0]), "r"(b[1]));
}

// Packed f32x2 (Blackwell): FFMA2 / FMUL2 are PTX-only paths.
__device__ __forceinline__ float2 f2fma(float2 a, float2 b, float2 c)
{
    float2 d;
    asm("fma.rn.f32x2 %0, %1, %2, %3;"
        : "=l"(reinterpret_cast<unsigned long long&>(d))
        : "l"(reinterpret_cast<unsigned long long&>(a)),
          "l"(reinterpret_cast<unsigned long long&>(b)),
          "l"(reinterpret_cast<unsigned long long&>(c)));
    return d;
}
__device__ __forceinline__ float2 f2mul(float2 a, float2 b)
{
    float2 d;
    asm("mul.rn.f32x2 %0, %1, %2;"
        : "=l"(reinterpret_cast<unsigned long long&>(d))
        : "l"(reinterpret_cast<unsigned long long&>(a)),
          "l"(reinterpret_cast<unsigned long long&>(b)));
    return d;
}

// ---------------------------------------------------------------------------
// Kernel 1: fused prep.
//   bid < 768            : 8 LN rows per block, one warp per row (no barriers)
//   bid in [768, 1920)   : weight split, one float4 per thread
// ---------------------------------------------------------------------------
constexpr int LN_ROW_BLOCKS = Bb * T / 8;                 // 768
constexpr int NSP       = DOUT * KSP;                     // 1048576
constexpr int WS_ELEMS  = NSP + DOUT * DIN;               // 1179648
constexpr int WS_BLOCKS = WS_ELEMS / 1024;                // 1152
constexpr int PREP_BLOCKS = LN_ROW_BLOCKS + WS_BLOCKS;    // 1920

__global__ void prep_kernel(const float* __restrict__ X,
                            const float* __restrict__ w,
                            const float* __restrict__ bias,
                            const float* __restrict__ spline_w,
                            const float* __restrict__ base_w,
                            const float* __restrict__ grid_rbf,
                            const float* __restrict__ grid_bs)
{
    int bid = blockIdx.x;
    int tid = threadIdx.x;

    if (bid >= LN_ROW_BLOCKS) {
        // ---- weight split: one float4 per thread ----
        int slot4 = (bid - LN_ROW_BLOCKS) * 256 + tid;    // 0 .. 294911
        int idx = slot4 * 4;
        const float* src = (idx < NSP) ? (spline_w + idx) : (base_w + (idx - NSP));
        float4 v = *reinterpret_cast<const float4*>(src);
        __nv_bfloat16 h0, l0, h1, l1, h2, l2, h3, l3;
        bsplit(v.x, h0, l0); bsplit(v.y, h1, l1);
        bsplit(v.z, h2, l2); bsplit(v.w, h3, l3);
        uint2 uh = make_uint2(pack2(h0, h1), pack2(h2, h3));
        uint2 ul = make_uint2(pack2(l0, l1), pack2(l2, l3));
        if (idx < NSP) {
            *reinterpret_cast<uint2*>(g_sw_hi + idx) = uh;
            *reinterpret_cast<uint2*>(g_sw_lo + idx) = ul;
        } else {
            int j = idx - NSP;
            *reinterpret_cast<uint2*>(g_bw_hi + j) = uh;
            *reinterpret_cast<uint2*>(g_bw_lo + j) = ul;
        }
        return;
    }

    // ---- LN: one warp per row ----
    int wid  = tid >> 5, lane = tid & 31;
    int row  = bid * 8 + wid;
    int bb   = row >> 10;
    int t    = row & 1023;
    const float* Xr = X + (size_t)row * DIN;

    float v[8];
    float s = 0.f, s2 = 0.f;
    #pragma unroll
    for (int j = 0; j < 8; j++) {
        v[j] = Xr[j * 32 + lane];
        s  += v[j];
        s2 += v[j] * v[j];
    }
    #pragma unroll
    for (int off = 16; off; off >>= 1) {
        s  += __shfl_xor_sync(0xffffffffu, s,  off);
        s2 += __shfl_xor_sync(0xffffffffu, s2, off);
    }
    float mu = s * (1.f / DIN);
    float rv = rsqrtf(s2 * (1.f / DIN) - mu * mu + 1e-5f);

    if (bb == 2) {
        #pragma unroll
        for (int j = 0; j < 8; j++) {
            int i = j * 32 + lane;
            float xn = (v[j] - mu) * rv * w[i] + bias[i];
            g_xn2[(size_t)t * DIN + i] = xn;
        }
        return;
    }
    if (bb == 3) {
        #pragma unroll
        for (int j = 0; j < 8; j++) {
            int i = j * 32 + lane;
            float xn = (v[j] - mu) * rv * w[i] + bias[i];
            float sig = 1.f / (1.f + __expf(-xn));
            __nv_bfloat16 h, l;
            bsplit(xn * sig, h, l);
            g_silu_hi[(size_t)t * DIN + i] = h;
            g_silu_lo[(size_t)t * DIN + i] = l;
        }
        return;
    }

    int slot = (bb == 0) ? 0 : (bb == 1) ? 1 : (bb == 4) ? 2 : 3;
    bool rbf = (bb == 0 || bb == 4);

    float gb[12], r1 = 0.f, r2 = 0.f, r3 = 0.f, gr[G];
    if (rbf) {
        #pragma unroll
        for (int g = 0; g < G; g++) gr[g] = __ldg(&grid_rbf[g]);
    } else {
        #pragma unroll
        for (int j = 0; j < 12; j++) gb[j] = __ldg(&grid_bs[j]);
        r1 = __fdividef(1.f, gb[1] - gb[0]);
        r2 = __fdividef(1.f, gb[2] - gb[0]);
        r3 = __fdividef(1.f, gb[3] - gb[0]);
    }

    #pragma unroll
    for (int j = 0; j < 8; j++) {
        int i = j * 32 + lane;
        float xn = (v[j] - mu) * rv * w[i] + bias[i];
        __nv_bfloat16 h[G], l[G];
        if (rbf) {
            const float invd = 7.f / 3.f;
            const float c    = -1.4426950408889634f;
            #pragma unroll
            for (int g = 0; g < G; g++) {
                float d = (xn - gr[g]) * invd;
                bsplit(exp2f(d * d * c), h[g], l[g]);
            }
        } else {
            float bsv[11];
            #pragma unroll
            for (int k = 0; k < 11; k++)
                bsv[k] = (xn >= gb[k] && xn < gb[k + 1]) ? 1.f : 0.f;
            #pragma unroll
            for (int k = 0; k <= 9; k++)
                bsv[k] = (xn - gb[k]) * r1 * bsv[k] + (gb[k + 2] - xn) * r1 * bsv[k + 1];
            #pragma unroll
            for (int k = 0; k <= 8; k++)
                bsv[k] = (xn - gb[k]) * r2 * bsv[k] + (gb[k + 3] - xn) * r2 * bsv[k + 1];
            #pragma unroll
            for (int k = 0; k <= 7; k++)
                bsv[k] = (xn - gb[k]) * r3 * bsv[k] + (gb[k + 4] - xn) * r3 * bsv[k + 1];
            #pragma unroll
            for (int k = 0; k < 8; k++) bsplit(bsv[k], h[k], l[k]);
        }
        size_t off = (size_t)slot * T * KSP + (size_t)t * KSP + i * 8;
        uint4 uh = make_uint4(pack2(h[0],h[1]), pack2(h[2],h[3]), pack2(h[4],h[5]), pack2(h[6],h[7]));
        uint4 ul = make_uint4(pack2(l[0],l[1]), pack2(l[2],l[3]), pack2(l[4],l[5]), pack2(l[6],l[7]));
        *reinterpret_cast<uint4*>(g_basis_hi + off) = uh;
        *reinterpret_cast<uint4*>(g_basis_lo + off) = ul;
    }
}

// ---------------------------------------------------------------------------
// Fat kernel: 64x128 gemm tiles (3-stage, 1 barrier/chunk, unchanged from R6)
// + 32x64 dog tiles (f32x2 packed), interleaved 5:4 over a period of 9.
// ---------------------------------------------------------------------------
constexpr int BM = 64, BN = 128, BK = 32;
constexpr int OFF_AH = 0, OFF_AL = 4096, OFF_WH = 8192, OFF_WL = 16384;
constexpr int STAGE  = 24576;
constexpr int NSTAGE = 3;
constexpr int SMEM_BYTES = NSTAGE * STAGE;   // 72 KB

constexpr int GEMM_TILES = 320;   // 256 spline + 64 base
constexpr int DOG_TILES  = 256;   // 16 o-tiles x 16 t-tiles (32 x 64)
constexpr int FAT_BLOCKS = GEMM_TILES + DOG_TILES;   // 576 = 9 * 64

__device__ __forceinline__ uint32_t swz(uint32_t row, uint32_t slot)
{
    return row * 64u + (((slot ^ ((row >> 1) & 3u)) & 3u) << 4);
}

__device__ __forceinline__ void gemm_path(int gidx, char* smem, float* __restrict__ out)
{
    uint32_t sbase = smem_u32(smem);
    int tid = threadIdx.x;

    int z, tt;
    if (gidx < 256) { z = gidx >> 6; tt = gidx & 63; }
    else            { z = 4;         tt = gidx - 256; }
    int mt = tt >> 2, nt = tt & 3;
    int bb = (z == 0) ? 0 : (z == 1) ? 1 : (z == 2) ? 4 : (z == 3) ? 5 : 3;

    const __nv_bfloat16 *Ah, *Al, *Wh, *Wl;
    int K;
    if (z < 4) {
        Ah = g_basis_hi + (size_t)z * T * KSP;
        Al = g_basis_lo + (size_t)z * T * KSP;
        Wh = g_sw_hi; Wl = g_sw_lo; K = KSP;
    } else {
        Ah = g_silu_hi; Al = g_silu_lo;
        Wh = g_bw_hi;  Wl = g_bw_lo;  K = DIN;
    }
    int m0 = mt * BM, n0 = nt * BN;
    int nc = K / BK;

    int lrow = tid >> 2, lslot = tid & 3;
    const __nv_bfloat16* gAh  = Ah + (size_t)(m0 + lrow) * K + lslot * 8;
    const __nv_bfloat16* gAl  = Al + (size_t)(m0 + lrow) * K + lslot * 8;
    const __nv_bfloat16* gW0h = Wh + (size_t)(n0 + lrow) * K + lslot * 8;
    const __nv_bfloat16* gW1h = Wh + (size_t)(n0 + lrow + 64) * K + lslot * 8;
    const __nv_bfloat16* gW0l = Wl + (size_t)(n0 + lrow) * K + lslot * 8;
    const __nv_bfloat16* gW1l = Wl + (size_t)(n0 + lrow + 64) * K + lslot * 8;
    uint32_t sA  = swz(lrow, lslot);
    uint32_t sW0 = swz(lrow, lslot);
    uint32_t sW1 = swz(lrow + 64, lslot);

    int lane = tid & 31, wid = tid >> 5;
    int wm = wid >> 2, wn = wid & 3;          // warp tile 32x32
    uint32_t lr  = lane & 15;
    uint32_t lks = lane >> 4;

    float acc[2][4][4];
    #pragma unroll
    for (int a = 0; a < 2; a++)
        #pragma unroll
        for (int b = 0; b < 4; b++)
            #pragma unroll
            for (int cc = 0; cc < 4; cc++) acc[a][b][cc] = 0.f;

    #pragma unroll
    for (int p = 0; p < 2; p++) {
        if (p < nc) {
            uint32_t sb = sbase + p * STAGE;
            int kc = p * BK;
            cpa(sb + OFF_AH + sA,  gAh + kc);
            cpa(sb + OFF_AL + sA,  gAl + kc);
            cpa(sb + OFF_WH + sW0, gW0h + kc);
            cpa(sb + OFF_WH + sW1, gW1h + kc);
            cpa(sb + OFF_WL + sW0, gW0l + kc);
            cpa(sb + OFF_WL + sW1, gW1l + kc);
        }
        CP_COMMIT();
    }

    int st = 0;
    for (int c = 0; c < nc; c++) {
        CP_WAIT1();
        __syncthreads();

        if (c + 2 < nc) {
            int stn = (st + 2 >= NSTAGE) ? st + 2 - NSTAGE : st + 2;
            uint32_t sb = sbase + stn * STAGE;
            int kc = (c + 2) * BK;
            cpa(sb + OFF_AH + sA,  gAh + kc);
            cpa(sb + OFF_AL + sA,  gAl + kc);
            cpa(sb + OFF_WH + sW0, gW0h + kc);
            cpa(sb + OFF_WH + sW1, gW1h + kc);
            cpa(sb + OFF_WL + sW0, gW0l + kc);
            cpa(sb + OFF_WL + sW1, gW1l + kc);
        }
        CP_COMMIT();

        uint32_t sb = sbase + st * STAGE;
        #pragma unroll
        for (int ks = 0; ks < 2; ks++) {
            uint32_t slot = 2 * ks + lks;
            uint32_t aF[2][4], bH[4][2], bL[4][2];

            #pragma unroll
            for (int mi = 0; mi < 2; mi++) {
                uint32_t ad = sb + OFF_AH + swz(wm * 32 + mi * 16 + lr, slot);
                LDSM_X4(aF[mi][0], aF[mi][1], aF[mi][2], aF[mi][3], ad);
            }
            #pragma unroll
            for (int p = 0; p < 2; p++) {
                uint32_t t0, t1, t2, t3;
                uint32_t ad = sb + OFF_WH + swz(wn * 32 + p * 16 + lr, slot);
                LDSM_X4(t0, t1, t2, t3, ad);
                bH[2*p][0] = t0; bH[2*p][1] = t2;
                bH[2*p+1][0] = t1; bH[2*p+1][1] = t3;
            }
            #pragma unroll
            for (int mi = 0; mi < 2; mi++)
                #pragma unroll
                for (int ni = 0; ni < 4; ni++)
                    mma16816(acc[mi][ni], aF[mi], bH[ni]);

            #pragma unroll
            for (int p = 0; p < 2; p++) {
                uint32_t t0, t1, t2, t3;
                uint32_t ad = sb + OFF_WL + swz(wn * 32 + p * 16 + lr, slot);
                LDSM_X4(t0, t1, t2, t3, ad);
                bL[2*p][0] = t0; bL[2*p][1] = t2;
                bL[2*p+1][0] = t1; bL[2*p+1][1] = t3;
            }
            #pragma unroll
            for (int mi = 0; mi < 2; mi++)
                #pragma unroll
                for (int ni = 0; ni < 4; ni++)
                    mma16816(acc[mi][ni], aF[mi], bL[ni]);

            #pragma unroll
            for (int mi = 0; mi < 2; mi++) {
                uint32_t ad = sb + OFF_AL + swz(wm * 32 + mi * 16 + lr, slot);
                LDSM_X4(aF[mi][0], aF[mi][1], aF[mi][2], aF[mi][3], ad);
            }
            #pragma unroll
            for (int mi = 0; mi < 2; mi++)
                #pragma unroll
                for (int ni = 0; ni < 4; ni++)
                    mma16816(acc[mi][ni], aF[mi], bH[ni]);
        }
        st = (st + 1 == NSTAGE) ? 0 : st + 1;
    }

    float* Cb = out + (size_t)bb * T * DOUT;
    int rbase = m0 + wm * 32 + (lane >> 2);
    int cbase = n0 + wn * 32 + (lane & 3) * 2;
    #pragma unroll
    for (int mi = 0; mi < 2; mi++) {
        #pragma unroll
        for (int ni = 0; ni < 4; ni++) {
            int r = rbase + mi * 16;
            int cc = cbase + ni * 8;
            *reinterpret_cast<float2*>(&Cb[(size_t)r * DOUT + cc]) =
                make_float2(acc[mi][ni][0], acc[mi][ni][1]);
            *reinterpret_cast<float2*>(&Cb[(size_t)(r + 8) * DOUT + cc]) =
                make_float2(acc[mi][ni][2], acc[mi][ni][3]);
        }
    }
}

// ---------------------------------------------------------------------------
// Dog path: 32 (o) x 64 (t) tiles, 8 t-rows per thread, f32x2 packed math.
// ---------------------------------------------------------------------------
struct DogS {
    float xn[64][33];
    float rs[32][33];
    float ntr[32][33];    // -trans*rs
    float nbw[32][33];    // -base_w
};

__device__ __forceinline__ void dog_path(int didx, char* smem,
                                         const float* __restrict__ base_w,
                                         const float* __restrict__ scale,
                                         const float* __restrict__ trans,
                                         float* __restrict__ out)
{
    DogS* S = reinterpret_cast<DogS*>(smem);   // double buffer S[0], S[1]
    int o0 = (didx & 15) * 32;
    int t0 = (didx >> 4) * 64;
    int tid = threadIdx.x;
    int tx = tid & 31, ty = tid >> 5;          // tx: o lane; ty: 8-row group
    int rX = tid >> 5, cX = tid & 31;          // xn loader base (64 rows via p)
    int rP = tid >> 5, cP = tid & 31;          // param loader base (32 rows via p)

    float2 acc[4];
    #pragma unroll
    for (int p = 0; p < 4; p++) acc[p] = make_float2(0.f, 0.f);
    const float Cc = -0.7213475204444817f;     // -0.5*log2(e)
    const float2 C2 = make_float2(Cc, Cc);

    float pxn[8], prs[4], ptr_[4], pbw[4];

    // prologue: chunk 0
    #pragma unroll
    for (int p = 0; p < 8; p++)
        pxn[p] = g_xn2[(size_t)(t0 + rX + p * 8) * DIN + cX];
    #pragma unroll
    for (int p = 0; p < 4; p++) {
        size_t oi = (size_t)(o0 + rP + p * 8) * DIN + cP;
        prs[p] = __fdividef(1.f, scale[oi]);
        ptr_[p] = trans[oi];
        pbw[p] = base_w[oi];
    }
    #pragma unroll
    for (int p = 0; p < 8; p++) S[0].xn[rX + p * 8][cX] = pxn[p];
    #pragma unroll
    for (int p = 0; p < 4; p++) {
        S[0].rs[rP + p * 8][cP]  = prs[p];
        S[0].ntr[rP + p * 8][cP] = -ptr_[p] * prs[p];
        S[0].nbw[rP + p * 8][cP] = -pbw[p];
    }

    for (int cc = 0; cc < DIN / 32; cc++) {
        __syncthreads();
        if (cc + 1 < DIN / 32) {
            int ic = (cc + 1) * 32;
            #pragma unroll
            for (int p = 0; p < 8; p++)
                pxn[p] = g_xn2[(size_t)(t0 + rX + p * 8) * DIN + ic + cX];
            #pragma unroll
            for (int p = 0; p < 4; p++) {
                size_t oi = (size_t)(o0 + rP + p * 8) * DIN + ic + cP;
                prs[p] = __fdividef(1.f, scale[oi]);
                ptr_[p] = trans[oi];
                pbw[p] = base_w[oi];
            }
        }

        DogS& B = S[cc & 1];
        #pragma unroll 4
        for (int i = 0; i < 32; i++) {
            float rsv = B.rs[tx][i];
            float ntr = B.ntr[tx][i];
            float nbw = B.nbw[tx][i];
            float2 rs2  = make_float2(rsv, rsv);
            float2 ntr2 = make_float2(ntr, ntr);
            float2 nbw2 = make_float2(nbw, nbw);
            #pragma unroll
            for (int p = 0; p < 4; p++) {
                float2 x2 = make_float2(B.xn[ty * 8 + 2 * p][i],
                                        B.xn[ty * 8 + 2 * p + 1][i]);
                float2 u  = f2fma(x2, rs2, ntr2);
                float2 t1 = f2mul(u, C2);
                float2 t2 = f2mul(t1, u);
                float2 e  = make_float2(exp2f(t2.x), exp2f(t2.y));
                float2 pe = f2mul(u, e);
                acc[p] = f2fma(pe, nbw2, acc[p]);
            }
        }

        if (cc + 1 < DIN / 32) {
            DogS& Bn = S[(cc + 1) & 1];
            #pragma unroll
            for (int p = 0; p < 8; p++) Bn.xn[rX + p * 8][cX] = pxn[p];
            #pragma unroll
            for (int p = 0; p < 4; p++) {
                Bn.rs[rP + p * 8][cP]  = prs[p];
                Bn.ntr[rP + p * 8][cP] = -ptr_[p] * prs[p];
                Bn.nbw[rP + p * 8][cP] = -pbw[p];
            }
        }
    }

    #pragma unroll
    for (int p = 0; p < 4; p++) {
        int r0 = t0 + ty * 8 + 2 * p;
        out[(size_t)(2 * T + r0) * DOUT + o0 + tx]     = acc[p].x;
        out[(size_t)(2 * T + r0 + 1) * DOUT + o0 + tx] = acc[p].y;
    }
}

__global__ void __launch_bounds__(256, 3)
fat_kernel(float* __restrict__ out,
           const float* __restrict__ base_w,
           const float* __restrict__ scale,
           const float* __restrict__ trans)
{
    extern __shared__ __align__(16) char smem[];
    int bid = blockIdx.x;
    int grp = bid / 9, rem = bid % 9;      // 576 = 9 * 64; 5 gemm + 4 dog
    if (rem < 5) gemm_path(grp * 5 + rem, smem, out);
    else         dog_path(grp * 4 + (rem - 5), smem, base_w, scale, trans, out);
}

// ---------------------------------------------------------------------------
extern "C" void kernel_launch(void* const* d_in, const int* in_sizes, int n_in,
                              void* d_out, int out_size)
{
    const float* X        = (const float*)d_in[0];
    const float* ln_w     = (const float*)d_in[1];
    const float* ln_b     = (const float*)d_in[2];
    const float* base_w   = (const float*)d_in[3];
    const float* spline_w = (const float*)d_in[4];
    const float* scale    = (const float*)d_in[5];
    const float* trans    = (const float*)d_in[6];
    const float* grid_rbf = (const float*)d_in[7];
    const float* grid_bs  = (const float*)d_in[8];
    float* out = (float*)d_out;

    cudaFuncSetAttribute(fat_kernel, cudaFuncAttributeMaxDynamicSharedMemorySize, SMEM_BYTES);

    prep_kernel<<<PREP_BLOCKS, 256>>>(X, ln_w, ln_b, spline_w, base_w,
                                      grid_rbf, grid_bs);
    fat_kernel<<<FAT_BLOCKS, 256, SMEM_BYTES>>>(out, base_w, scale, trans);
}

// round 8
// speedup vs baseline: 1.7765x; 1.2562x over previous
#include <cuda_runtime.h>
#include <cuda_fp16.h>
#include <cstdint>

// Problem constants
constexpr int Bb   = 6;
constexpr int T    = 1024;
constexpr int DIN  = 256;
constexpr int DOUT = 512;
constexpr int G    = 8;
constexpr int KSP  = DIN * G;   // 2048

// ---------------------------------------------------------------------------
// Device scratch
// ---------------------------------------------------------------------------
__device__ __align__(16) float   g_xn2[T * DIN];             // LN'd batch 2 (dog)
__device__ __align__(16) __half  g_silu[T * DIN];            // fp16 silu (batch 3)
__device__ __align__(16) __half  g_basis[4ull * T * KSP];    // fp16 basis, slots 0..3
__device__ __align__(16) __half  g_sw_hi[DOUT * KSP];
__device__ __align__(16) __half  g_sw_lo[DOUT * KSP];
__device__ __align__(16) __half  g_bw_hi[DOUT * DIN];
__device__ __align__(16) __half  g_bw_lo[DOUT * DIN];

// ---------------------------------------------------------------------------
// Helpers
// ---------------------------------------------------------------------------
__device__ __forceinline__ void hsplit(float x, __half& h, __half& l)
{
    __half hb = __float2half_rn(x);
    h = hb;
    l = __float2half_rn(x - __half2float(hb));
}

__device__ __forceinline__ uint32_t hpack2(__half a, __half b)
{
    __half2 p = __halves2half2(a, b);
    return *reinterpret_cast<uint32_t*>(&p);
}

__device__ __forceinline__ uint32_t smem_u32(const void* p)
{
    uint32_t a;
    asm("{ .reg .u64 t; cvta.to.shared.u64 t, %1; cvt.u32.u64 %0, t; }" : "=r"(a) : "l"(p));
    return a;
}

__device__ __forceinline__ void cpa(uint32_t d, const void* s)
{
    asm volatile("cp.async.cg.shared.global [%0], [%1], 16;" :: "r"(d), "l"(s));
}
#define CP_COMMIT() asm volatile("cp.async.commit_group;" ::: "memory")
#define CP_WAIT1()  asm volatile("cp.async.wait_group 1;"  ::: "memory")

#define LDSM_X4(R0,R1,R2,R3,ADDR) \
    asm volatile("ldmatrix.sync.aligned.m8n8.x4.shared.b16 {%0,%1,%2,%3}, [%4];" \
        : "=r"(R0), "=r"(R1), "=r"(R2), "=r"(R3) : "r"(ADDR))

__device__ __forceinline__ void mma16816(float* c, const uint32_t* a, const uint32_t* b)
{
    asm volatile(
        "mma.sync.aligned.m16n8k16.row.col.f32.f16.f16.f32 "
        "{%0,%1,%2,%3}, {%4,%5,%6,%7}, {%8,%9}, {%0,%1,%2,%3};"
        : "+f"(c[0]), "+f"(c[1]), "+f"(c[2]), "+f"(c[3])
        : "r"(a[0]), "r"(a[1]), "r"(a[2]), "r"(a[3]), "r"(b[0]), "r"(b[1]));
}

// Packed f32x2 (Blackwell)
__device__ __forceinline__ float2 f2fma(float2 a, float2 b, float2 c)
{
    float2 d;
    asm("fma.rn.f32x2 %0, %1, %2, %3;"
        : "=l"(reinterpret_cast<unsigned long long&>(d))
        : "l"(reinterpret_cast<unsigned long long&>(a)),
          "l"(reinterpret_cast<unsigned long long&>(b)),
          "l"(reinterpret_cast<unsigned long long&>(c)));
    return d;
}
__device__ __forceinline__ float2 f2mul(float2 a, float2 b)
{
    float2 d;
    asm("mul.rn.f32x2 %0, %1, %2;"
        : "=l"(reinterpret_cast<unsigned long long&>(d))
        : "l"(reinterpret_cast<unsigned long long&>(a)),
          "l"(reinterpret_cast<unsigned long long&>(b)));
    return d;
}

// ---------------------------------------------------------------------------
// Kernel 1: fused prep.
//   bid < 768            : 8 LN rows per block, one warp per row
//   bid in [768, 1920)   : weight split (fp16 hi/lo), one float4 per thread
// ---------------------------------------------------------------------------
constexpr int LN_ROW_BLOCKS = Bb * T / 8;                 // 768
constexpr int NSP       = DOUT * KSP;                     // 1048576
constexpr int WS_ELEMS  = NSP + DOUT * DIN;               // 1179648
constexpr int WS_BLOCKS = WS_ELEMS / 1024;                // 1152
constexpr int PREP_BLOCKS = LN_ROW_BLOCKS + WS_BLOCKS;    // 1920

__global__ void prep_kernel(const float* __restrict__ X,
                            const float* __restrict__ w,
                            const float* __restrict__ bias,
                            const float* __restrict__ spline_w,
                            const float* __restrict__ base_w,
                            const float* __restrict__ grid_rbf,
                            const float* __restrict__ grid_bs)
{
    int bid = blockIdx.x;
    int tid = threadIdx.x;

    if (bid >= LN_ROW_BLOCKS) {
        // ---- weight split: one float4 per thread ----
        int slot4 = (bid - LN_ROW_BLOCKS) * 256 + tid;
        int idx = slot4 * 4;
        const float* src = (idx < NSP) ? (spline_w + idx) : (base_w + (idx - NSP));
        float4 v = *reinterpret_cast<const float4*>(src);
        __half h0, l0, h1, l1, h2, l2, h3, l3;
        hsplit(v.x, h0, l0); hsplit(v.y, h1, l1);
        hsplit(v.z, h2, l2); hsplit(v.w, h3, l3);
        uint2 uh = make_uint2(hpack2(h0, h1), hpack2(h2, h3));
        uint2 ul = make_uint2(hpack2(l0, l1), hpack2(l2, l3));
        if (idx < NSP) {
            *reinterpret_cast<uint2*>(g_sw_hi + idx) = uh;
            *reinterpret_cast<uint2*>(g_sw_lo + idx) = ul;
        } else {
            int j = idx - NSP;
            *reinterpret_cast<uint2*>(g_bw_hi + j) = uh;
            *reinterpret_cast<uint2*>(g_bw_lo + j) = ul;
        }
        return;
    }

    // ---- LN: one warp per row ----
    int wid  = tid >> 5, lane = tid & 31;
    int row  = bid * 8 + wid;
    int bb   = row >> 10;
    int t    = row & 1023;
    const float* Xr = X + (size_t)row * DIN;

    float v[8];
    float s = 0.f, s2 = 0.f;
    #pragma unroll
    for (int j = 0; j < 8; j++) {
        v[j] = Xr[j * 32 + lane];
        s  += v[j];
        s2 += v[j] * v[j];
    }
    #pragma unroll
    for (int off = 16; off; off >>= 1) {
        s  += __shfl_xor_sync(0xffffffffu, s,  off);
        s2 += __shfl_xor_sync(0xffffffffu, s2, off);
    }
    float mu = s * (1.f / DIN);
    float rv = rsqrtf(s2 * (1.f / DIN) - mu * mu + 1e-5f);

    if (bb == 2) {
        #pragma unroll
        for (int j = 0; j < 8; j++) {
            int i = j * 32 + lane;
            float xn = (v[j] - mu) * rv * w[i] + bias[i];
            g_xn2[(size_t)t * DIN + i] = xn;
        }
        return;
    }
    if (bb == 3) {
        #pragma unroll
        for (int j = 0; j < 8; j++) {
            int i = j * 32 + lane;
            float xn = (v[j] - mu) * rv * w[i] + bias[i];
            float sig = 1.f / (1.f + __expf(-xn));
            g_silu[(size_t)t * DIN + i] = __float2half_rn(xn * sig);
        }
        return;
    }

    int slot = (bb == 0) ? 0 : (bb == 1) ? 1 : (bb == 4) ? 2 : 3;
    bool rbf = (bb == 0 || bb == 4);

    float gb[12], r1 = 0.f, r2 = 0.f, r3 = 0.f, gr[G];
    if (rbf) {
        #pragma unroll
        for (int g = 0; g < G; g++) gr[g] = __ldg(&grid_rbf[g]);
    } else {
        #pragma unroll
        for (int j = 0; j < 12; j++) gb[j] = __ldg(&grid_bs[j]);
        r1 = __fdividef(1.f, gb[1] - gb[0]);
        r2 = __fdividef(1.f, gb[2] - gb[0]);
        r3 = __fdividef(1.f, gb[3] - gb[0]);
    }

    #pragma unroll
    for (int j = 0; j < 8; j++) {
        int i = j * 32 + lane;
        float xn = (v[j] - mu) * rv * w[i] + bias[i];
        __half h[G];
        if (rbf) {
            const float invd = 7.f / 3.f;
            const float c    = -1.4426950408889634f;
            #pragma unroll
            for (int g = 0; g < G; g++) {
                float d = (xn - gr[g]) * invd;
                h[g] = __float2half_rn(exp2f(d * d * c));
            }
        } else {
            float bsv[11];
            #pragma unroll
            for (int k = 0; k < 11; k++)
                bsv[k] = (xn >= gb[k] && xn < gb[k + 1]) ? 1.f : 0.f;
            #pragma unroll
            for (int k = 0; k <= 9; k++)
                bsv[k] = (xn - gb[k]) * r1 * bsv[k] + (gb[k + 2] - xn) * r1 * bsv[k + 1];
            #pragma unroll
            for (int k = 0; k <= 8; k++)
                bsv[k] = (xn - gb[k]) * r2 * bsv[k] + (gb[k + 3] - xn) * r2 * bsv[k + 1];
            #pragma unroll
            for (int k = 0; k <= 7; k++)
                bsv[k] = (xn - gb[k]) * r3 * bsv[k] + (gb[k + 4] - xn) * r3 * bsv[k + 1];
            #pragma unroll
            for (int k = 0; k < 8; k++) h[k] = __float2half_rn(bsv[k]);
        }
        size_t off = (size_t)slot * T * KSP + (size_t)t * KSP + i * 8;
        uint4 uh = make_uint4(hpack2(h[0],h[1]), hpack2(h[2],h[3]),
                              hpack2(h[4],h[5]), hpack2(h[6],h[7]));
        *reinterpret_cast<uint4*>(g_basis + off) = uh;
    }
}

// ---------------------------------------------------------------------------
// Fat kernel: 64x128 fp16 gemm tiles (2-term split, 3-stage, 1 barrier/chunk)
// + 32x64 dog tiles (f32x2 packed), interleaved 5:4 over a period of 9.
// ---------------------------------------------------------------------------
constexpr int BM = 64, BN = 128, BK = 32;
constexpr int OFF_AH = 0, OFF_WH = 4096, OFF_WL = 12288;
constexpr int STAGE  = 20480;
constexpr int NSTAGE = 3;
constexpr int SMEM_BYTES = NSTAGE * STAGE;   // 60 KB

constexpr int GEMM_TILES = 320;   // 256 spline + 64 base
constexpr int DOG_TILES  = 256;   // 16 o-tiles x 16 t-tiles (32 x 64)
constexpr int FAT_BLOCKS = GEMM_TILES + DOG_TILES;   // 576 = 9 * 64

__device__ __forceinline__ uint32_t swz(uint32_t row, uint32_t slot)
{
    return row * 64u + (((slot ^ ((row >> 1) & 3u)) & 3u) << 4);
}

__device__ __forceinline__ void gemm_path(int gidx, char* smem, float* __restrict__ out)
{
    uint32_t sbase = smem_u32(smem);
    int tid = threadIdx.x;

    int z, tt;
    if (gidx < 256) { z = gidx >> 6; tt = gidx & 63; }
    else            { z = 4;         tt = gidx - 256; }
    int mt = tt >> 2, nt = tt & 3;
    int bb = (z == 0) ? 0 : (z == 1) ? 1 : (z == 2) ? 4 : (z == 3) ? 5 : 3;

    const __half *Ah, *Wh, *Wl;
    int K;
    if (z < 4) {
        Ah = g_basis + (size_t)z * T * KSP;
        Wh = g_sw_hi; Wl = g_sw_lo; K = KSP;
    } else {
        Ah = g_silu;
        Wh = g_bw_hi; Wl = g_bw_lo; K = DIN;
    }
    int m0 = mt * BM, n0 = nt * BN;
    int nc = K / BK;

    int lrow = tid >> 2, lslot = tid & 3;
    const __half* gAh  = Ah + (size_t)(m0 + lrow) * K + lslot * 8;
    const __half* gW0h = Wh + (size_t)(n0 + lrow) * K + lslot * 8;
    const __half* gW1h = Wh + (size_t)(n0 + lrow + 64) * K + lslot * 8;
    const __half* gW0l = Wl + (size_t)(n0 + lrow) * K + lslot * 8;
    const __half* gW1l = Wl + (size_t)(n0 + lrow + 64) * K + lslot * 8;
    uint32_t sA  = swz(lrow, lslot);
    uint32_t sW0 = swz(lrow, lslot);
    uint32_t sW1 = swz(lrow + 64, lslot);

    int lane = tid & 31, wid = tid >> 5;
    int wm = wid >> 2, wn = wid & 3;          // warp tile 32x32
    uint32_t lr  = lane & 15;
    uint32_t lks = lane >> 4;

    float acc[2][4][4];
    #pragma unroll
    for (int a = 0; a < 2; a++)
        #pragma unroll
        for (int b = 0; b < 4; b++)
            #pragma unroll
            for (int cc = 0; cc < 4; cc++) acc[a][b][cc] = 0.f;

    #pragma unroll
    for (int p = 0; p < 2; p++) {
        if (p < nc) {
            uint32_t sb = sbase + p * STAGE;
            int kc = p * BK;
            cpa(sb + OFF_AH + sA,  gAh + kc);
            cpa(sb + OFF_WH + sW0, gW0h + kc);
            cpa(sb + OFF_WH + sW1, gW1h + kc);
            cpa(sb + OFF_WL + sW0, gW0l + kc);
            cpa(sb + OFF_WL + sW1, gW1l + kc);
        }
        CP_COMMIT();
    }

    int st = 0;
    for (int c = 0; c < nc; c++) {
        CP_WAIT1();
        __syncthreads();

        if (c + 2 < nc) {
            int stn = (st + 2 >= NSTAGE) ? st + 2 - NSTAGE : st + 2;
            uint32_t sb = sbase + stn * STAGE;
            int kc = (c + 2) * BK;
            cpa(sb + OFF_AH + sA,  gAh + kc);
            cpa(sb + OFF_WH + sW0, gW0h + kc);
            cpa(sb + OFF_WH + sW1, gW1h + kc);
            cpa(sb + OFF_WL + sW0, gW0l + kc);
            cpa(sb + OFF_WL + sW1, gW1l + kc);
        }
        CP_COMMIT();

        uint32_t sb = sbase + st * STAGE;
        #pragma unroll
        for (int ks = 0; ks < 2; ks++) {
            uint32_t slot = 2 * ks + lks;
            uint32_t aF[2][4], bH[4][2], bL[4][2];

            #pragma unroll
            for (int mi = 0; mi < 2; mi++) {
                uint32_t ad = sb + OFF_AH + swz(wm * 32 + mi * 16 + lr, slot);
                LDSM_X4(aF[mi][0], aF[mi][1], aF[mi][2], aF[mi][3], ad);
            }
            #pragma unroll
            for (int p = 0; p < 2; p++) {
                uint32_t t0, t1, t2, t3;
                uint32_t ad = sb + OFF_WH + swz(wn * 32 + p * 16 + lr, slot);
                LDSM_X4(t0, t1, t2, t3, ad);
                bH[2*p][0] = t0; bH[2*p][1] = t2;
                bH[2*p+1][0] = t1; bH[2*p+1][1] = t3;
            }
            // term 1: Ah * Wh
            #pragma unroll
            for (int mi = 0; mi < 2; mi++)
                #pragma unroll
                for (int ni = 0; ni < 4; ni++)
                    mma16816(acc[mi][ni], aF[mi], bH[ni]);

            #pragma unroll
            for (int p = 0; p < 2; p++) {
                uint32_t t0, t1, t2, t3;
                uint32_t ad = sb + OFF_WL + swz(wn * 32 + p * 16 + lr, slot);
                LDSM_X4(t0, t1, t2, t3, ad);
                bL[2*p][0] = t0; bL[2*p][1] = t2;
                bL[2*p+1][0] = t1; bL[2*p+1][1] = t3;
            }
            // term 2: Ah * Wl
            #pragma unroll
            for (int mi = 0; mi < 2; mi++)
                #pragma unroll
                for (int ni = 0; ni < 4; ni++)
                    mma16816(acc[mi][ni], aF[mi], bL[ni]);
        }
        st = (st + 1 == NSTAGE) ? 0 : st + 1;
    }

    float* Cb = out + (size_t)bb * T * DOUT;
    int rbase = m0 + wm * 32 + (lane >> 2);
    int cbase = n0 + wn * 32 + (lane & 3) * 2;
    #pragma unroll
    for (int mi = 0; mi < 2; mi++) {
        #pragma unroll
        for (int ni = 0; ni < 4; ni++) {
            int r = rbase + mi * 16;
            int cc = cbase + ni * 8;
            *reinterpret_cast<float2*>(&Cb[(size_t)r * DOUT + cc]) =
                make_float2(acc[mi][ni][0], acc[mi][ni][1]);
            *reinterpret_cast<float2*>(&Cb[(size_t)(r + 8) * DOUT + cc]) =
                make_float2(acc[mi][ni][2], acc[mi][ni][3]);
        }
    }
}

// ---------------------------------------------------------------------------
// Dog path: 32 (o) x 64 (t) tiles, 8 t-rows per thread, f32x2 packed math.
// ---------------------------------------------------------------------------
struct DogS {
    float xn[64][33];
    float rs[32][33];
    float ntr[32][33];    // -trans*rs
    float nbw[32][33];    // -base_w
};

__device__ __forceinline__ void dog_path(int didx, char* smem,
                                         const float* __restrict__ base_w,
                                         const float* __restrict__ scale,
                                         const float* __restrict__ trans,
                                         float* __restrict__ out)
{
    DogS* S = reinterpret_cast<DogS*>(smem);   // double buffer S[0], S[1]
    int o0 = (didx & 15) * 32;
    int t0 = (didx >> 4) * 64;
    int tid = threadIdx.x;
    int tx = tid & 31, ty = tid >> 5;
    int rX = tid >> 5, cX = tid & 31;

    float2 acc[4];
    #pragma unroll
    for (int p = 0; p < 4; p++) acc[p] = make_float2(0.f, 0.f);
    const float Cc = -0.7213475204444817f;     // -0.5*log2(e)
    const float2 C2 = make_float2(Cc, Cc);

    float pxn[8], prs[4], ptr_[4], pbw[4];

    #pragma unroll
    for (int p = 0; p < 8; p++)
        pxn[p] = g_xn2[(size_t)(t0 + rX + p * 8) * DIN + cX];
    #pragma unroll
    for (int p = 0; p < 4; p++) {
        size_t oi = (size_t)(o0 + rX + p * 8) * DIN + cX;
        prs[p] = __fdividef(1.f, scale[oi]);
        ptr_[p] = trans[oi];
        pbw[p] = base_w[oi];
    }
    #pragma unroll
    for (int p = 0; p < 8; p++) S[0].xn[rX + p * 8][cX] = pxn[p];
    #pragma unroll
    for (int p = 0; p < 4; p++) {
        S[0].rs[rX + p * 8][cX]  = prs[p];
        S[0].ntr[rX + p * 8][cX] = -ptr_[p] * prs[p];
        S[0].nbw[rX + p * 8][cX] = -pbw[p];
    }

    for (int cc = 0; cc < DIN / 32; cc++) {
        __syncthreads();
        if (cc + 1 < DIN / 32) {
            int ic = (cc + 1) * 32;
            #pragma unroll
            for (int p = 0; p < 8; p++)
                pxn[p] = g_xn2[(size_t)(t0 + rX + p * 8) * DIN + ic + cX];
            #pragma unroll
            for (int p = 0; p < 4; p++) {
                size_t oi = (size_t)(o0 + rX + p * 8) * DIN + ic + cX;
                prs[p] = __fdividef(1.f, scale[oi]);
                ptr_[p] = trans[oi];
                pbw[p] = base_w[oi];
            }
        }

        DogS& B = S[cc & 1];
        #pragma unroll 4
        for (int i = 0; i < 32; i++) {
            float rsv = B.rs[tx][i];
            float ntr = B.ntr[tx][i];
            float nbw = B.nbw[tx][i];
            float2 rs2  = make_float2(rsv, rsv);
            float2 ntr2 = make_float2(ntr, ntr);
            float2 nbw2 = make_float2(nbw, nbw);
            #pragma unroll
            for (int p = 0; p < 4; p++) {
                float2 x2 = make_float2(B.xn[ty * 8 + 2 * p][i],
                                        B.xn[ty * 8 + 2 * p + 1][i]);
                float2 u  = f2fma(x2, rs2, ntr2);
                float2 t1 = f2mul(u, C2);
                float2 t2 = f2mul(t1, u);
                float2 e  = make_float2(exp2f(t2.x), exp2f(t2.y));
                float2 pe = f2mul(u, e);
                acc[p] = f2fma(pe, nbw2, acc[p]);
            }
        }

        if (cc + 1 < DIN / 32) {
            DogS& Bn = S[(cc + 1) & 1];
            #pragma unroll
            for (int p = 0; p < 8; p++) Bn.xn[rX + p * 8][cX] = pxn[p];
            #pragma unroll
            for (int p = 0; p < 4; p++) {
                Bn.rs[rX + p * 8][cX]  = prs[p];
                Bn.ntr[rX + p * 8][cX] = -ptr_[p] * prs[p];
                Bn.nbw[rX + p * 8][cX] = -pbw[p];
            }
        }
    }

    #pragma unroll
    for (int p = 0; p < 4; p++) {
        int r0 = t0 + ty * 8 + 2 * p;
        out[(size_t)(2 * T + r0) * DOUT + o0 + tx]     = acc[p].x;
        out[(size_t)(2 * T + r0 + 1) * DOUT + o0 + tx] = acc[p].y;
    }
}

__global__ void __launch_bounds__(256, 3)
fat_kernel(float* __restrict__ out,
           const float* __restrict__ base_w,
           const float* __restrict__ scale,
           const float* __restrict__ trans)
{
    extern __shared__ __align__(16) char smem[];
    int bid = blockIdx.x;
    int grp = bid / 9, rem = bid % 9;      // 576 = 9 * 64; 5 gemm + 4 dog
    if (rem < 5) gemm_path(grp * 5 + rem, smem, out);
    else         dog_path(grp * 4 + (rem - 5), smem, base_w, scale, trans, out);
}

// ---------------------------------------------------------------------------
extern "C" void kernel_launch(void* const* d_in, const int* in_sizes, int n_in,
                              void* d_out, int out_size)
{
    const float* X        = (const float*)d_in[0];
    const float* ln_w     = (const float*)d_in[1];
    const float* ln_b     = (const float*)d_in[2];
    const float* base_w   = (const float*)d_in[3];
    const float* spline_w = (const float*)d_in[4];
    const float* scale    = (const float*)d_in[5];
    const float* trans    = (const float*)d_in[6];
    const float* grid_rbf = (const float*)d_in[7];
    const float* grid_bs  = (const float*)d_in[8];
    float* out = (float*)d_out;

    cudaFuncSetAttribute(fat_kernel, cudaFuncAttributeMaxDynamicSharedMemorySize, SMEM_BYTES);

    prep_kernel<<<PREP_BLOCKS, 256>>>(X, ln_w, ln_b, spline_w, base_w,
                                      grid_rbf, grid_bs);
    fat_kernel<<<FAT_BLOCKS, 256, SMEM_BYTES>>>(out, base_w, scale, trans);
}

// round 9
// speedup vs baseline: 1.8404x; 1.0360x over previous
#include <cuda_runtime.h>
#include <cuda_fp16.h>
#include <cstdint>

// Problem constants
constexpr int Bb   = 6;
constexpr int T    = 1024;
constexpr int DIN  = 256;
constexpr int DOUT = 512;
constexpr int G    = 8;
constexpr int KSP  = DIN * G;   // 2048

// ---------------------------------------------------------------------------
// Device scratch
// ---------------------------------------------------------------------------
__device__ __align__(16) float   g_xn2[T * DIN];             // LN'd batch 2 (dog)
__device__ __align__(16) __half  g_silu[T * DIN];            // fp16 silu (batch 3)
__device__ __align__(16) __half  g_basis[4ull * T * KSP];    // fp16 basis, slots 0..3
__device__ __align__(16) __half  g_sw_hi[DOUT * KSP];
__device__ __align__(16) __half  g_sw_lo[DOUT * KSP];
__device__ __align__(16) __half  g_bw_hi[DOUT * DIN];
__device__ __align__(16) __half  g_bw_lo[DOUT * DIN];

// ---------------------------------------------------------------------------
// Helpers
// ---------------------------------------------------------------------------
__device__ __forceinline__ void hsplit(float x, __half& h, __half& l)
{
    __half hb = __float2half_rn(x);
    h = hb;
    l = __float2half_rn(x - __half2float(hb));
}

__device__ __forceinline__ uint32_t hpack2(__half a, __half b)
{
    __half2 p = __halves2half2(a, b);
    return *reinterpret_cast<uint32_t*>(&p);
}

__device__ __forceinline__ uint32_t smem_u32(const void* p)
{
    uint32_t a;
    asm("{ .reg .u64 t; cvta.to.shared.u64 t, %1; cvt.u32.u64 %0, t; }" : "=r"(a) : "l"(p));
    return a;
}

__device__ __forceinline__ void cpa(uint32_t d, const void* s)
{
    asm volatile("cp.async.cg.shared.global [%0], [%1], 16;" :: "r"(d), "l"(s));
}
#define CP_COMMIT() asm volatile("cp.async.commit_group;" ::: "memory")
#define CP_WAIT1()  asm volatile("cp.async.wait_group 1;"  ::: "memory")

#define LDSM_X4(R0,R1,R2,R3,ADDR) \
    asm volatile("ldmatrix.sync.aligned.m8n8.x4.shared.b16 {%0,%1,%2,%3}, [%4];" \
        : "=r"(R0), "=r"(R1), "=r"(R2), "=r"(R3) : "r"(ADDR))

__device__ __forceinline__ void mma16816(float* c, const uint32_t* a, const uint32_t* b)
{
    asm volatile(
        "mma.sync.aligned.m16n8k16.row.col.f32.f16.f16.f32 "
        "{%0,%1,%2,%3}, {%4,%5,%6,%7}, {%8,%9}, {%0,%1,%2,%3};"
        : "+f"(c[0]), "+f"(c[1]), "+f"(c[2]), "+f"(c[3])
        : "r"(a[0]), "r"(a[1]), "r"(a[2]), "r"(a[3]), "r"(b[0]), "r"(b[1]));
}

// Packed f32x2 (Blackwell)
__device__ __forceinline__ float2 f2fma(float2 a, float2 b, float2 c)
{
    float2 d;
    asm("fma.rn.f32x2 %0, %1, %2, %3;"
        : "=l"(reinterpret_cast<unsigned long long&>(d))
        : "l"(reinterpret_cast<unsigned long long&>(a)),
          "l"(reinterpret_cast<unsigned long long&>(b)),
          "l"(reinterpret_cast<unsigned long long&>(c)));
    return d;
}
__device__ __forceinline__ float2 f2mul(float2 a, float2 b)
{
    float2 d;
    asm("mul.rn.f32x2 %0, %1, %2;"
        : "=l"(reinterpret_cast<unsigned long long&>(d))
        : "l"(reinterpret_cast<unsigned long long&>(a)),
          "l"(reinterpret_cast<unsigned long long&>(b)));
    return d;
}

// ---------------------------------------------------------------------------
// Kernel 1: fused prep.
//   bid < 768            : 8 LN rows per block, one warp per row
//   bid in [768, 1920)   : weight split (fp16 hi/lo), one float4 per thread
// ---------------------------------------------------------------------------
constexpr int LN_ROW_BLOCKS = Bb * T / 8;                 // 768
constexpr int NSP       = DOUT * KSP;                     // 1048576
constexpr int WS_ELEMS  = NSP + DOUT * DIN;               // 1179648
constexpr int WS_BLOCKS = WS_ELEMS / 1024;                // 1152
constexpr int PREP_BLOCKS = LN_ROW_BLOCKS + WS_BLOCKS;    // 1920

__global__ void prep_kernel(const float* __restrict__ X,
                            const float* __restrict__ w,
                            const float* __restrict__ bias,
                            const float* __restrict__ spline_w,
                            const float* __restrict__ base_w,
                            const float* __restrict__ grid_rbf,
                            const float* __restrict__ grid_bs)
{
    int bid = blockIdx.x;
    int tid = threadIdx.x;

    if (bid >= LN_ROW_BLOCKS) {
        // ---- weight split: one float4 per thread ----
        int slot4 = (bid - LN_ROW_BLOCKS) * 256 + tid;
        int idx = slot4 * 4;
        const float* src = (idx < NSP) ? (spline_w + idx) : (base_w + (idx - NSP));
        float4 v = *reinterpret_cast<const float4*>(src);
        __half h0, l0, h1, l1, h2, l2, h3, l3;
        hsplit(v.x, h0, l0); hsplit(v.y, h1, l1);
        hsplit(v.z, h2, l2); hsplit(v.w, h3, l3);
        uint2 uh = make_uint2(hpack2(h0, h1), hpack2(h2, h3));
        uint2 ul = make_uint2(hpack2(l0, l1), hpack2(l2, l3));
        if (idx < NSP) {
            *reinterpret_cast<uint2*>(g_sw_hi + idx) = uh;
            *reinterpret_cast<uint2*>(g_sw_lo + idx) = ul;
        } else {
            int j = idx - NSP;
            *reinterpret_cast<uint2*>(g_bw_hi + j) = uh;
            *reinterpret_cast<uint2*>(g_bw_lo + j) = ul;
        }
        return;
    }

    // ---- LN: one warp per row ----
    int wid  = tid >> 5, lane = tid & 31;
    int row  = bid * 8 + wid;
    int bb   = row >> 10;
    int t    = row & 1023;
    const float* Xr = X + (size_t)row * DIN;

    float v[8];
    float s = 0.f, s2 = 0.f;
    #pragma unroll
    for (int j = 0; j < 8; j++) {
        v[j] = Xr[j * 32 + lane];
        s  += v[j];
        s2 += v[j] * v[j];
    }
    #pragma unroll
    for (int off = 16; off; off >>= 1) {
        s  += __shfl_xor_sync(0xffffffffu, s,  off);
        s2 += __shfl_xor_sync(0xffffffffu, s2, off);
    }
    float mu = s * (1.f / DIN);
    float rv = rsqrtf(s2 * (1.f / DIN) - mu * mu + 1e-5f);

    if (bb == 2) {
        #pragma unroll
        for (int j = 0; j < 8; j++) {
            int i = j * 32 + lane;
            float xn = (v[j] - mu) * rv * w[i] + bias[i];
            g_xn2[(size_t)t * DIN + i] = xn;
        }
        return;
    }
    if (bb == 3) {
        #pragma unroll
        for (int j = 0; j < 8; j++) {
            int i = j * 32 + lane;
            float xn = (v[j] - mu) * rv * w[i] + bias[i];
            float sig = 1.f / (1.f + __expf(-xn));
            g_silu[(size_t)t * DIN + i] = __float2half_rn(xn * sig);
        }
        return;
    }

    int slot = (bb == 0) ? 0 : (bb == 1) ? 1 : (bb == 4) ? 2 : 3;
    bool rbf = (bb == 0 || bb == 4);

    float gb[12], r1 = 0.f, r2 = 0.f, r3 = 0.f, gr[G];
    if (rbf) {
        #pragma unroll
        for (int g = 0; g < G; g++) gr[g] = __ldg(&grid_rbf[g]);
    } else {
        #pragma unroll
        for (int j = 0; j < 12; j++) gb[j] = __ldg(&grid_bs[j]);
        r1 = __fdividef(1.f, gb[1] - gb[0]);
        r2 = __fdividef(1.f, gb[2] - gb[0]);
        r3 = __fdividef(1.f, gb[3] - gb[0]);
    }

    #pragma unroll
    for (int j = 0; j < 8; j++) {
        int i = j * 32 + lane;
        float xn = (v[j] - mu) * rv * w[i] + bias[i];
        __half h[G];
        if (rbf) {
            const float invd = 7.f / 3.f;
            const float c    = -1.4426950408889634f;
            #pragma unroll
            for (int g = 0; g < G; g++) {
                float d = (xn - gr[g]) * invd;
                h[g] = __float2half_rn(exp2f(d * d * c));
            }
        } else {
            float bsv[11];
            #pragma unroll
            for (int k = 0; k < 11; k++)
                bsv[k] = (xn >= gb[k] && xn < gb[k + 1]) ? 1.f : 0.f;
            #pragma unroll
            for (int k = 0; k <= 9; k++)
                bsv[k] = (xn - gb[k]) * r1 * bsv[k] + (gb[k + 2] - xn) * r1 * bsv[k + 1];
            #pragma unroll
            for (int k = 0; k <= 8; k++)
                bsv[k] = (xn - gb[k]) * r2 * bsv[k] + (gb[k + 3] - xn) * r2 * bsv[k + 1];
            #pragma unroll
            for (int k = 0; k <= 7; k++)
                bsv[k] = (xn - gb[k]) * r3 * bsv[k] + (gb[k + 4] - xn) * r3 * bsv[k + 1];
            #pragma unroll
            for (int k = 0; k < 8; k++) h[k] = __float2half_rn(bsv[k]);
        }
        size_t off = (size_t)slot * T * KSP + (size_t)t * KSP + i * 8;
        uint4 uh = make_uint4(hpack2(h[0],h[1]), hpack2(h[2],h[3]),
                              hpack2(h[4],h[5]), hpack2(h[6],h[7]));
        *reinterpret_cast<uint4*>(g_basis + off) = uh;
    }
}

// ---------------------------------------------------------------------------
// Fat kernel: 64x128 fp16 gemm tiles (2-term split, 3-stage, 1 barrier/chunk)
// + 32x64 dog tiles (f32x2 packed, LDS.128 layout), interleaved 5:4.
// ---------------------------------------------------------------------------
constexpr int BM = 64, BN = 128, BK = 32;
constexpr int OFF_AH = 0, OFF_WH = 4096, OFF_WL = 12288;
constexpr int STAGE  = 20480;
constexpr int NSTAGE = 3;
constexpr int SMEM_BYTES = NSTAGE * STAGE;   // 60 KB

constexpr int GEMM_TILES = 320;   // 256 spline + 64 base
constexpr int DOG_TILES  = 256;   // 16 o-tiles x 16 t-tiles (32 x 64)
constexpr int FAT_BLOCKS = GEMM_TILES + DOG_TILES;   // 576 = 9 * 64

__device__ __forceinline__ uint32_t swz(uint32_t row, uint32_t slot)
{
    return row * 64u + (((slot ^ ((row >> 1) & 3u)) & 3u) << 4);
}

__device__ __forceinline__ void gemm_path(int gidx, char* smem, float* __restrict__ out)
{
    uint32_t sbase = smem_u32(smem);
    int tid = threadIdx.x;

    int z, tt;
    if (gidx < 256) { z = gidx >> 6; tt = gidx & 63; }
    else            { z = 4;         tt = gidx - 256; }
    int mt = tt >> 2, nt = tt & 3;
    int bb = (z == 0) ? 0 : (z == 1) ? 1 : (z == 2) ? 4 : (z == 3) ? 5 : 3;

    const __half *Ah, *Wh, *Wl;
    int K;
    if (z < 4) {
        Ah = g_basis + (size_t)z * T * KSP;
        Wh = g_sw_hi; Wl = g_sw_lo; K = KSP;
    } else {
        Ah = g_silu;
        Wh = g_bw_hi; Wl = g_bw_lo; K = DIN;
    }
    int m0 = mt * BM, n0 = nt * BN;
    int nc = K / BK;

    int lrow = tid >> 2, lslot = tid & 3;
    const __half* gAh  = Ah + (size_t)(m0 + lrow) * K + lslot * 8;
    const __half* gW0h = Wh + (size_t)(n0 + lrow) * K + lslot * 8;
    const __half* gW1h = Wh + (size_t)(n0 + lrow + 64) * K + lslot * 8;
    const __half* gW0l = Wl + (size_t)(n0 + lrow) * K + lslot * 8;
    const __half* gW1l = Wl + (size_t)(n0 + lrow + 64) * K + lslot * 8;
    uint32_t sA  = swz(lrow, lslot);
    uint32_t sW0 = swz(lrow, lslot);
    uint32_t sW1 = swz(lrow + 64, lslot);

    int lane = tid & 31, wid = tid >> 5;
    int wm = wid >> 2, wn = wid & 3;          // warp tile 32x32
    uint32_t lr  = lane & 15;
    uint32_t lks = lane >> 4;

    float acc[2][4][4];
    #pragma unroll
    for (int a = 0; a < 2; a++)
        #pragma unroll
        for (int b = 0; b < 4; b++)
            #pragma unroll
            for (int cc = 0; cc < 4; cc++) acc[a][b][cc] = 0.f;

    #pragma unroll
    for (int p = 0; p < 2; p++) {
        if (p < nc) {
            uint32_t sb = sbase + p * STAGE;
            int kc = p * BK;
            cpa(sb + OFF_AH + sA,  gAh + kc);
            cpa(sb + OFF_WH + sW0, gW0h + kc);
            cpa(sb + OFF_WH + sW1, gW1h + kc);
            cpa(sb + OFF_WL + sW0, gW0l + kc);
            cpa(sb + OFF_WL + sW1, gW1l + kc);
        }
        CP_COMMIT();
    }

    int st = 0;
    for (int c = 0; c < nc; c++) {
        CP_WAIT1();
        __syncthreads();

        if (c + 2 < nc) {
            int stn = (st + 2 >= NSTAGE) ? st + 2 - NSTAGE : st + 2;
            uint32_t sb = sbase + stn * STAGE;
            int kc = (c + 2) * BK;
            cpa(sb + OFF_AH + sA,  gAh + kc);
            cpa(sb + OFF_WH + sW0, gW0h + kc);
            cpa(sb + OFF_WH + sW1, gW1h + kc);
            cpa(sb + OFF_WL + sW0, gW0l + kc);
            cpa(sb + OFF_WL + sW1, gW1l + kc);
        }
        CP_COMMIT();

        uint32_t sb = sbase + st * STAGE;
        #pragma unroll
        for (int ks = 0; ks < 2; ks++) {
            uint32_t slot = 2 * ks + lks;
            uint32_t aF[2][4], bH[4][2], bL[4][2];

            #pragma unroll
            for (int mi = 0; mi < 2; mi++) {
                uint32_t ad = sb + OFF_AH + swz(wm * 32 + mi * 16 + lr, slot);
                LDSM_X4(aF[mi][0], aF[mi][1], aF[mi][2], aF[mi][3], ad);
            }
            #pragma unroll
            for (int p = 0; p < 2; p++) {
                uint32_t t0, t1, t2, t3;
                uint32_t ad = sb + OFF_WH + swz(wn * 32 + p * 16 + lr, slot);
                LDSM_X4(t0, t1, t2, t3, ad);
                bH[2*p][0] = t0; bH[2*p][1] = t2;
                bH[2*p+1][0] = t1; bH[2*p+1][1] = t3;
            }
            // term 1: Ah * Wh
            #pragma unroll
            for (int mi = 0; mi < 2; mi++)
                #pragma unroll
                for (int ni = 0; ni < 4; ni++)
                    mma16816(acc[mi][ni], aF[mi], bH[ni]);

            #pragma unroll
            for (int p = 0; p < 2; p++) {
                uint32_t t0, t1, t2, t3;
                uint32_t ad = sb + OFF_WL + swz(wn * 32 + p * 16 + lr, slot);
                LDSM_X4(t0, t1, t2, t3, ad);
                bL[2*p][0] = t0; bL[2*p][1] = t2;
                bL[2*p+1][0] = t1; bL[2*p+1][1] = t3;
            }
            // term 2: Ah * Wl
            #pragma unroll
            for (int mi = 0; mi < 2; mi++)
                #pragma unroll
                for (int ni = 0; ni < 4; ni++)
                    mma16816(acc[mi][ni], aF[mi], bL[ni]);
        }
        st = (st + 1 == NSTAGE) ? 0 : st + 1;
    }

    float* Cb = out + (size_t)bb * T * DOUT;
    int rbase = m0 + wm * 32 + (lane >> 2);
    int cbase = n0 + wn * 32 + (lane & 3) * 2;
    #pragma unroll
    for (int mi = 0; mi < 2; mi++) {
        #pragma unroll
        for (int ni = 0; ni < 4; ni++) {
            int r = rbase + mi * 16;
            int cc = cbase + ni * 8;
            *reinterpret_cast<float2*>(&Cb[(size_t)r * DOUT + cc]) =
                make_float2(acc[mi][ni][0], acc[mi][ni][1]);
            *reinterpret_cast<float2*>(&Cb[(size_t)(r + 8) * DOUT + cc]) =
                make_float2(acc[mi][ni][2], acc[mi][ni][3]);
        }
    }
}

// ---------------------------------------------------------------------------
// Dog path: 32 (o) x 64 (t) tiles, f32x2 packed math, LDS.128-optimized:
//   xn transposed [i][t_local] (stride 72) -> 2 broadcast LDS.128 per i
//   params packed (rs, -tr*rs, -bw, 0) as float4 [o][i] -> 1 LDS.128 per i
// ---------------------------------------------------------------------------
struct DogS {
    float  xn[32][72];     // [i][t_local]
    float4 pq[32][33];     // [o_local][i]
};

__device__ __forceinline__ void dog_path(int didx, char* smem,
                                         const float* __restrict__ base_w,
                                         const float* __restrict__ scale,
                                         const float* __restrict__ trans,
                                         float* __restrict__ out)
{
    DogS* S = reinterpret_cast<DogS*>(smem);   // double buffer S[0], S[1]
    int o0 = (didx & 15) * 32;
    int t0 = (didx >> 4) * 64;
    int tid = threadIdx.x;
    int tx = tid & 31, ty = tid >> 5;
    int rX = tid >> 5, cX = tid & 31;

    float2 acc[4];
    #pragma unroll
    for (int p = 0; p < 4; p++) acc[p] = make_float2(0.f, 0.f);
    const float Cc = -0.7213475204444817f;     // -0.5*log2(e)
    const float2 C2 = make_float2(Cc, Cc);

    float pxn[8], prs[4], ptr_[4], pbw[4];

    // prologue: chunk 0
    #pragma unroll
    for (int p = 0; p < 8; p++)
        pxn[p] = g_xn2[(size_t)(t0 + rX + p * 8) * DIN + cX];
    #pragma unroll
    for (int p = 0; p < 4; p++) {
        size_t oi = (size_t)(o0 + rX + p * 8) * DIN + cX;
        prs[p] = __fdividef(1.f, scale[oi]);
        ptr_[p] = trans[oi];
        pbw[p] = base_w[oi];
    }
    #pragma unroll
    for (int p = 0; p < 8; p++) S[0].xn[cX][rX + p * 8] = pxn[p];
    #pragma unroll
    for (int p = 0; p < 4; p++)
        S[0].pq[rX + p * 8][cX] = make_float4(prs[p], -ptr_[p] * prs[p], -pbw[p], 0.f);

    for (int cc = 0; cc < DIN / 32; cc++) {
        __syncthreads();
        if (cc + 1 < DIN / 32) {
            int ic = (cc + 1) * 32;
            #pragma unroll
            for (int p = 0; p < 8; p++)
                pxn[p] = g_xn2[(size_t)(t0 + rX + p * 8) * DIN + ic + cX];
            #pragma unroll
            for (int p = 0; p < 4; p++) {
                size_t oi = (size_t)(o0 + rX + p * 8) * DIN + ic + cX;
                prs[p] = __fdividef(1.f, scale[oi]);
                ptr_[p] = trans[oi];
                pbw[p] = base_w[oi];
            }
        }

        DogS& B = S[cc & 1];
        #pragma unroll 4
        for (int i = 0; i < 32; i++) {
            float4 pq = B.pq[tx][i];
            float2 rs2  = make_float2(pq.x, pq.x);
            float2 ntr2 = make_float2(pq.y, pq.y);
            float2 nbw2 = make_float2(pq.z, pq.z);
            const float4* xp = reinterpret_cast<const float4*>(&B.xn[i][ty * 8]);
            float4 xa = xp[0];
            float4 xb = xp[1];
            float2 xs[4] = { make_float2(xa.x, xa.y), make_float2(xa.z, xa.w),
                             make_float2(xb.x, xb.y), make_float2(xb.z, xb.w) };
            #pragma unroll
            for (int p = 0; p < 4; p++) {
                float2 u  = f2fma(xs[p], rs2, ntr2);
                float2 t1 = f2mul(u, C2);
                float2 t2 = f2mul(t1, u);
                float2 e  = make_float2(exp2f(t2.x), exp2f(t2.y));
                float2 pe = f2mul(u, e);
                acc[p] = f2fma(pe, nbw2, acc[p]);
            }
        }

        if (cc + 1 < DIN / 32) {
            DogS& Bn = S[(cc + 1) & 1];
            #pragma unroll
            for (int p = 0; p < 8; p++) Bn.xn[cX][rX + p * 8] = pxn[p];
            #pragma unroll
            for (int p = 0; p < 4; p++)
                Bn.pq[rX + p * 8][cX] = make_float4(prs[p], -ptr_[p] * prs[p], -pbw[p], 0.f);
        }
    }

    #pragma unroll
    for (int p = 0; p < 4; p++) {
        int r0 = t0 + ty * 8 + 2 * p;
        out[(size_t)(2 * T + r0) * DOUT + o0 + tx]     = acc[p].x;
        out[(size_t)(2 * T + r0 + 1) * DOUT + o0 + tx] = acc[p].y;
    }
}

__global__ void __launch_bounds__(256, 3)
fat_kernel(float* __restrict__ out,
           const float* __restrict__ base_w,
           const float* __restrict__ scale,
           const float* __restrict__ trans)
{
    extern __shared__ __align__(16) char smem[];
    int bid = blockIdx.x;
    int grp = bid / 9, rem = bid % 9;      // 576 = 9 * 64; 5 gemm + 4 dog
    if (rem < 5) gemm_path(grp * 5 + rem, smem, out);
    else         dog_path(grp * 4 + (rem - 5), smem, base_w, scale, trans, out);
}

// ---------------------------------------------------------------------------
extern "C" void kernel_launch(void* const* d_in, const int* in_sizes, int n_in,
                              void* d_out, int out_size)
{
    const float* X        = (const float*)d_in[0];
    const float* ln_w     = (const float*)d_in[1];
    const float* ln_b     = (const float*)d_in[2];
    const float* base_w   = (const float*)d_in[3];
    const float* spline_w = (const float*)d_in[4];
    const float* scale    = (const float*)d_in[5];
    const float* trans    = (const float*)d_in[6];
    const float* grid_rbf = (const float*)d_in[7];
    const float* grid_bs  = (const float*)d_in[8];
    float* out = (float*)d_out;

    cudaFuncSetAttribute(fat_kernel, cudaFuncAttributeMaxDynamicSharedMemorySize, SMEM_BYTES);

    prep_kernel<<<PREP_BLOCKS, 256>>>(X, ln_w, ln_b, spline_w, base_w,
                                      grid_rbf, grid_bs);
    fat_kernel<<<FAT_BLOCKS, 256, SMEM_BYTES>>>(out, base_w, scale, trans);
}

// round 10
// speedup vs baseline: 2.0959x; 1.1388x over previous
#include <cuda_runtime.h>
#include <cuda_fp16.h>
#include <cstdint>

// Problem constants
constexpr int Bb   = 6;
constexpr int T    = 1024;
constexpr int DIN  = 256;
constexpr int DOUT = 512;
constexpr int G    = 8;
constexpr int KSP  = DIN * G;   // 2048

// ---------------------------------------------------------------------------
// Device scratch
// ---------------------------------------------------------------------------
__device__ __align__(16) float   g_xn2[T * DIN];             // LN'd batch 2 (dog)
__device__ __align__(16) __half  g_silu[T * DIN];            // fp16 silu (batch 3)
__device__ __align__(16) __half  g_basis[4ull * T * KSP];    // fp16 basis, slots 0..3
__device__ __align__(16) __half  g_sw[DOUT * KSP];           // fp16 spline weight
__device__ __align__(16) __half  g_bw[DOUT * DIN];           // fp16 base weight

// ---------------------------------------------------------------------------
// Helpers
// ---------------------------------------------------------------------------
__device__ __forceinline__ uint32_t hpack2(__half a, __half b)
{
    __half2 p = __halves2half2(a, b);
    return *reinterpret_cast<uint32_t*>(&p);
}

__device__ __forceinline__ uint32_t smem_u32(const void* p)
{
    uint32_t a;
    asm("{ .reg .u64 t; cvta.to.shared.u64 t, %1; cvt.u32.u64 %0, t; }" : "=r"(a) : "l"(p));
    return a;
}

__device__ __forceinline__ void cpa(uint32_t d, const void* s)
{
    asm volatile("cp.async.cg.shared.global [%0], [%1], 16;" :: "r"(d), "l"(s));
}
#define CP_COMMIT() asm volatile("cp.async.commit_group;" ::: "memory")
#define CP_WAIT1()  asm volatile("cp.async.wait_group 1;"  ::: "memory")

#define LDSM_X4(R0,R1,R2,R3,ADDR) \
    asm volatile("ldmatrix.sync.aligned.m8n8.x4.shared.b16 {%0,%1,%2,%3}, [%4];" \
        : "=r"(R0), "=r"(R1), "=r"(R2), "=r"(R3) : "r"(ADDR))

__device__ __forceinline__ void mma16816(float* c, const uint32_t* a, const uint32_t* b)
{
    asm volatile(
        "mma.sync.aligned.m16n8k16.row.col.f32.f16.f16.f32 "
        "{%0,%1,%2,%3}, {%4,%5,%6,%7}, {%8,%9}, {%0,%1,%2,%3};"
        : "+f"(c[0]), "+f"(c[1]), "+f"(c[2]), "+f"(c[3])
        : "r"(a[0]), "r"(a[1]), "r"(a[2]), "r"(a[3]), "r"(b[0]), "r"(b[1]));
}

// Packed f32x2 (Blackwell)
__device__ __forceinline__ float2 f2fma(float2 a, float2 b, float2 c)
{
    float2 d;
    asm("fma.rn.f32x2 %0, %1, %2, %3;"
        : "=l"(reinterpret_cast<unsigned long long&>(d))
        : "l"(reinterpret_cast<unsigned long long&>(a)),
          "l"(reinterpret_cast<unsigned long long&>(b)),
          "l"(reinterpret_cast<unsigned long long&>(c)));
    return d;
}
__device__ __forceinline__ float2 f2mul(float2 a, float2 b)
{
    float2 d;
    asm("mul.rn.f32x2 %0, %1, %2;"
        : "=l"(reinterpret_cast<unsigned long long&>(d))
        : "l"(reinterpret_cast<unsigned long long&>(a)),
          "l"(reinterpret_cast<unsigned long long&>(b)));
    return d;
}

// ---------------------------------------------------------------------------
// Kernel 1: fused prep.
//   bid < 768            : 8 LN rows per block, one warp per row
//   bid in [768, 1920)   : weight convert fp32 -> fp16, one float4 per thread
// ---------------------------------------------------------------------------
constexpr int LN_ROW_BLOCKS = Bb * T / 8;                 // 768
constexpr int NSP       = DOUT * KSP;                     // 1048576
constexpr int WS_ELEMS  = NSP + DOUT * DIN;               // 1179648
constexpr int WS_BLOCKS = WS_ELEMS / 1024;                // 1152
constexpr int PREP_BLOCKS = LN_ROW_BLOCKS + WS_BLOCKS;    // 1920

__global__ void prep_kernel(const float* __restrict__ X,
                            const float* __restrict__ w,
                            const float* __restrict__ bias,
                            const float* __restrict__ spline_w,
                            const float* __restrict__ base_w,
                            const float* __restrict__ grid_rbf,
                            const float* __restrict__ grid_bs)
{
    int bid = blockIdx.x;
    int tid = threadIdx.x;

    if (bid >= LN_ROW_BLOCKS) {
        // ---- weight convert: one float4 per thread ----
        int slot4 = (bid - LN_ROW_BLOCKS) * 256 + tid;
        int idx = slot4 * 4;
        const float* src = (idx < NSP) ? (spline_w + idx) : (base_w + (idx - NSP));
        float4 v = *reinterpret_cast<const float4*>(src);
        uint2 uh = make_uint2(hpack2(__float2half_rn(v.x), __float2half_rn(v.y)),
                              hpack2(__float2half_rn(v.z), __float2half_rn(v.w)));
        if (idx < NSP) {
            *reinterpret_cast<uint2*>(g_sw + idx) = uh;
        } else {
            *reinterpret_cast<uint2*>(g_bw + (idx - NSP)) = uh;
        }
        return;
    }

    // ---- LN: one warp per row ----
    int wid  = tid >> 5, lane = tid & 31;
    int row  = bid * 8 + wid;
    int bb   = row >> 10;
    int t    = row & 1023;
    const float* Xr = X + (size_t)row * DIN;

    float v[8];
    float s = 0.f, s2 = 0.f;
    #pragma unroll
    for (int j = 0; j < 8; j++) {
        v[j] = Xr[j * 32 + lane];
        s  += v[j];
        s2 += v[j] * v[j];
    }
    #pragma unroll
    for (int off = 16; off; off >>= 1) {
        s  += __shfl_xor_sync(0xffffffffu, s,  off);
        s2 += __shfl_xor_sync(0xffffffffu, s2, off);
    }
    float mu = s * (1.f / DIN);
    float rv = rsqrtf(s2 * (1.f / DIN) - mu * mu + 1e-5f);

    if (bb == 2) {
        #pragma unroll
        for (int j = 0; j < 8; j++) {
            int i = j * 32 + lane;
            float xn = (v[j] - mu) * rv * w[i] + bias[i];
            g_xn2[(size_t)t * DIN + i] = xn;
        }
        return;
    }
    if (bb == 3) {
        #pragma unroll
        for (int j = 0; j < 8; j++) {
            int i = j * 32 + lane;
            float xn = (v[j] - mu) * rv * w[i] + bias[i];
            float sig = 1.f / (1.f + __expf(-xn));
            g_silu[(size_t)t * DIN + i] = __float2half_rn(xn * sig);
        }
        return;
    }

    int slot = (bb == 0) ? 0 : (bb == 1) ? 1 : (bb == 4) ? 2 : 3;
    bool rbf = (bb == 0 || bb == 4);

    float gb[12], r1 = 0.f, r2 = 0.f, r3 = 0.f, gr[G];
    if (rbf) {
        #pragma unroll
        for (int g = 0; g < G; g++) gr[g] = __ldg(&grid_rbf[g]);
    } else {
        #pragma unroll
        for (int j = 0; j < 12; j++) gb[j] = __ldg(&grid_bs[j]);
        r1 = __fdividef(1.f, gb[1] - gb[0]);
        r2 = __fdividef(1.f, gb[2] - gb[0]);
        r3 = __fdividef(1.f, gb[3] - gb[0]);
    }

    #pragma unroll
    for (int j = 0; j < 8; j++) {
        int i = j * 32 + lane;
        float xn = (v[j] - mu) * rv * w[i] + bias[i];
        __half h[G];
        if (rbf) {
            const float invd = 7.f / 3.f;
            const float c    = -1.4426950408889634f;
            #pragma unroll
            for (int g = 0; g < G; g++) {
                float d = (xn - gr[g]) * invd;
                h[g] = __float2half_rn(exp2f(d * d * c));
            }
        } else {
            float bsv[11];
            #pragma unroll
            for (int k = 0; k < 11; k++)
                bsv[k] = (xn >= gb[k] && xn < gb[k + 1]) ? 1.f : 0.f;
            #pragma unroll
            for (int k = 0; k <= 9; k++)
                bsv[k] = (xn - gb[k]) * r1 * bsv[k] + (gb[k + 2] - xn) * r1 * bsv[k + 1];
            #pragma unroll
            for (int k = 0; k <= 8; k++)
                bsv[k] = (xn - gb[k]) * r2 * bsv[k] + (gb[k + 3] - xn) * r2 * bsv[k + 1];
            #pragma unroll
            for (int k = 0; k <= 7; k++)
                bsv[k] = (xn - gb[k]) * r3 * bsv[k] + (gb[k + 4] - xn) * r3 * bsv[k + 1];
            #pragma unroll
            for (int k = 0; k < 8; k++) h[k] = __float2half_rn(bsv[k]);
        }
        size_t off = (size_t)slot * T * KSP + (size_t)t * KSP + i * 8;
        uint4 uh = make_uint4(hpack2(h[0],h[1]), hpack2(h[2],h[3]),
                              hpack2(h[4],h[5]), hpack2(h[6],h[7]));
        *reinterpret_cast<uint4*>(g_basis + off) = uh;
    }
}

// ---------------------------------------------------------------------------
// Fat kernel: 64x128 fp16 gemm tiles (single-term, 3-stage, 1 barrier/chunk)
// + 32x64 dog tiles (f32x2 packed, LDS.128 layout), interleaved 5:4.
// ---------------------------------------------------------------------------
constexpr int BM = 64, BN = 128, BK = 32;
constexpr int OFF_A = 0, OFF_W = 4096;
constexpr int STAGE  = 12288;
constexpr int NSTAGE = 3;
constexpr int SMEM_BYTES = 53248;            // max(gemm 36 KB, dog 52.2 KB)

constexpr int GEMM_TILES = 320;   // 256 spline + 64 base
constexpr int DOG_TILES  = 256;   // 16 o-tiles x 16 t-tiles (32 x 64)
constexpr int FAT_BLOCKS = GEMM_TILES + DOG_TILES;   // 576 = 9 * 64

__device__ __forceinline__ uint32_t swz(uint32_t row, uint32_t slot)
{
    return row * 64u + (((slot ^ ((row >> 1) & 3u)) & 3u) << 4);
}

__device__ __forceinline__ void gemm_path(int gidx, char* smem, float* __restrict__ out)
{
    uint32_t sbase = smem_u32(smem);
    int tid = threadIdx.x;

    int z, tt;
    if (gidx < 256) { z = gidx >> 6; tt = gidx & 63; }
    else            { z = 4;         tt = gidx - 256; }
    int mt = tt >> 2, nt = tt & 3;
    int bb = (z == 0) ? 0 : (z == 1) ? 1 : (z == 2) ? 4 : (z == 3) ? 5 : 3;

    const __half *A, *W;
    int K;
    if (z < 4) {
        A = g_basis + (size_t)z * T * KSP;
        W = g_sw; K = KSP;
    } else {
        A = g_silu;
        W = g_bw; K = DIN;
    }
    int m0 = mt * BM, n0 = nt * BN;
    int nc = K / BK;

    int lrow = tid >> 2, lslot = tid & 3;
    const __half* gA  = A + (size_t)(m0 + lrow) * K + lslot * 8;
    const __half* gW0 = W + (size_t)(n0 + lrow) * K + lslot * 8;
    const __half* gW1 = W + (size_t)(n0 + lrow + 64) * K + lslot * 8;
    uint32_t sA  = swz(lrow, lslot);
    uint32_t sW0 = swz(lrow, lslot);
    uint32_t sW1 = swz(lrow + 64, lslot);

    int lane = tid & 31, wid = tid >> 5;
    int wm = wid >> 2, wn = wid & 3;          // warp tile 32x32
    uint32_t lr  = lane & 15;
    uint32_t lks = lane >> 4;

    float acc[2][4][4];
    #pragma unroll
    for (int a = 0; a < 2; a++)
        #pragma unroll
        for (int b = 0; b < 4; b++)
            #pragma unroll
            for (int cc = 0; cc < 4; cc++) acc[a][b][cc] = 0.f;

    #pragma unroll
    for (int p = 0; p < 2; p++) {
        if (p < nc) {
            uint32_t sb = sbase + p * STAGE;
            int kc = p * BK;
            cpa(sb + OFF_A + sA,  gA + kc);
            cpa(sb + OFF_W + sW0, gW0 + kc);
            cpa(sb + OFF_W + sW1, gW1 + kc);
        }
        CP_COMMIT();
    }

    int st = 0;
    for (int c = 0; c < nc; c++) {
        CP_WAIT1();
        __syncthreads();

        if (c + 2 < nc) {
            int stn = (st + 2 >= NSTAGE) ? st + 2 - NSTAGE : st + 2;
            uint32_t sb = sbase + stn * STAGE;
            int kc = (c + 2) * BK;
            cpa(sb + OFF_A + sA,  gA + kc);
            cpa(sb + OFF_W + sW0, gW0 + kc);
            cpa(sb + OFF_W + sW1, gW1 + kc);
        }
        CP_COMMIT();

        uint32_t sb = sbase + st * STAGE;
        #pragma unroll
        for (int ks = 0; ks < 2; ks++) {
            uint32_t slot = 2 * ks + lks;
            uint32_t aF[2][4], bF[4][2];

            #pragma unroll
            for (int mi = 0; mi < 2; mi++) {
                uint32_t ad = sb + OFF_A + swz(wm * 32 + mi * 16 + lr, slot);
                LDSM_X4(aF[mi][0], aF[mi][1], aF[mi][2], aF[mi][3], ad);
            }
            #pragma unroll
            for (int p = 0; p < 2; p++) {
                uint32_t t0, t1, t2, t3;
                uint32_t ad = sb + OFF_W + swz(wn * 32 + p * 16 + lr, slot);
                LDSM_X4(t0, t1, t2, t3, ad);
                bF[2*p][0] = t0; bF[2*p][1] = t2;
                bF[2*p+1][0] = t1; bF[2*p+1][1] = t3;
            }
            #pragma unroll
            for (int mi = 0; mi < 2; mi++)
                #pragma unroll
                for (int ni = 0; ni < 4; ni++)
                    mma16816(acc[mi][ni], aF[mi], bF[ni]);
        }
        st = (st + 1 == NSTAGE) ? 0 : st + 1;
    }

    float* Cb = out + (size_t)bb * T * DOUT;
    int rbase = m0 + wm * 32 + (lane >> 2);
    int cbase = n0 + wn * 32 + (lane & 3) * 2;
    #pragma unroll
    for (int mi = 0; mi < 2; mi++) {
        #pragma unroll
        for (int ni = 0; ni < 4; ni++) {
            int r = rbase + mi * 16;
            int cc = cbase + ni * 8;
            *reinterpret_cast<float2*>(&Cb[(size_t)r * DOUT + cc]) =
                make_float2(acc[mi][ni][0], acc[mi][ni][1]);
            *reinterpret_cast<float2*>(&Cb[(size_t)(r + 8) * DOUT + cc]) =
                make_float2(acc[mi][ni][2], acc[mi][ni][3]);
        }
    }
}

// ---------------------------------------------------------------------------
// Dog path: 32 (o) x 64 (t) tiles, f32x2 packed math, LDS.128-optimized:
//   xn transposed [i][t_local] (stride 72) -> 2 broadcast LDS.128 per i
//   params packed (rs, -tr*rs, -bw, 0) as float4 [o][i] -> 1 LDS.128 per i
// ---------------------------------------------------------------------------
struct DogS {
    float  xn[32][72];     // [i][t_local]
    float4 pq[32][33];     // [o_local][i]
};

__device__ __forceinline__ void dog_path(int didx, char* smem,
                                         const float* __restrict__ base_w,
                                         const float* __restrict__ scale,
                                         const float* __restrict__ trans,
                                         float* __restrict__ out)
{
    DogS* S = reinterpret_cast<DogS*>(smem);   // double buffer S[0], S[1]
    int o0 = (didx & 15) * 32;
    int t0 = (didx >> 4) * 64;
    int tid = threadIdx.x;
    int tx = tid & 31, ty = tid >> 5;
    int rX = tid >> 5, cX = tid & 31;

    float2 acc[4];
    #pragma unroll
    for (int p = 0; p < 4; p++) acc[p] = make_float2(0.f, 0.f);
    const float Cc = -0.7213475204444817f;     // -0.5*log2(e)
    const float2 C2 = make_float2(Cc, Cc);

    float pxn[8], prs[4], ptr_[4], pbw[4];

    // prologue: chunk 0
    #pragma unroll
    for (int p = 0; p < 8; p++)
        pxn[p] = g_xn2[(size_t)(t0 + rX + p * 8) * DIN + cX];
    #pragma unroll
    for (int p = 0; p < 4; p++) {
        size_t oi = (size_t)(o0 + rX + p * 8) * DIN + cX;
        prs[p] = __fdividef(1.f, scale[oi]);
        ptr_[p] = trans[oi];
        pbw[p] = base_w[oi];
    }
    #pragma unroll
    for (int p = 0; p < 8; p++) S[0].xn[cX][rX + p * 8] = pxn[p];
    #pragma unroll
    for (int p = 0; p < 4; p++)
        S[0].pq[rX + p * 8][cX] = make_float4(prs[p], -ptr_[p] * prs[p], -pbw[p], 0.f);

    for (int cc = 0; cc < DIN / 32; cc++) {
        __syncthreads();
        if (cc + 1 < DIN / 32) {
            int ic = (cc + 1) * 32;
            #pragma unroll
            for (int p = 0; p < 8; p++)
                pxn[p] = g_xn2[(size_t)(t0 + rX + p * 8) * DIN + ic + cX];
            #pragma unroll
            for (int p = 0; p < 4; p++) {
                size_t oi = (size_t)(o0 + rX + p * 8) * DIN + ic + cX;
                prs[p] = __fdividef(1.f, scale[oi]);
                ptr_[p] = trans[oi];
                pbw[p] = base_w[oi];
            }
        }

        DogS& B = S[cc & 1];
        #pragma unroll 4
        for (int i = 0; i < 32; i++) {
            float4 pq = B.pq[tx][i];
            float2 rs2  = make_float2(pq.x, pq.x);
            float2 ntr2 = make_float2(pq.y, pq.y);
            float2 nbw2 = make_float2(pq.z, pq.z);
            const float4* xp = reinterpret_cast<const float4*>(&B.xn[i][ty * 8]);
            float4 xa = xp[0];
            float4 xb = xp[1];
            float2 xs[4] = { make_float2(xa.x, xa.y), make_float2(xa.z, xa.w),
                             make_float2(xb.x, xb.y), make_float2(xb.z, xb.w) };
            #pragma unroll
            for (int p = 0; p < 4; p++) {
                float2 u  = f2fma(xs[p], rs2, ntr2);
                float2 t1 = f2mul(u, C2);
                float2 t2 = f2mul(t1, u);
                float2 e  = make_float2(exp2f(t2.x), exp2f(t2.y));
                float2 pe = f2mul(u, e);
                acc[p] = f2fma(pe, nbw2, acc[p]);
            }
        }

        if (cc + 1 < DIN / 32) {
            DogS& Bn = S[(cc + 1) & 1];
            #pragma unroll
            for (int p = 0; p < 8; p++) Bn.xn[cX][rX + p * 8] = pxn[p];
            #pragma unroll
            for (int p = 0; p < 4; p++)
                Bn.pq[rX + p * 8][cX] = make_float4(prs[p], -ptr_[p] * prs[p], -pbw[p], 0.f);
        }
    }

    #pragma unroll
    for (int p = 0; p < 4; p++) {
        int r0 = t0 + ty * 8 + 2 * p;
        out[(size_t)(2 * T + r0) * DOUT + o0 + tx]     = acc[p].x;
        out[(size_t)(2 * T + r0 + 1) * DOUT + o0 + tx] = acc[p].y;
    }
}

__global__ void __launch_bounds__(256, 3)
fat_kernel(float* __restrict__ out,
           const float* __restrict__ base_w,
           const float* __restrict__ scale,
           const float* __restrict__ trans)
{
    extern __shared__ __align__(16) char smem[];
    int bid = blockIdx.x;
    int grp = bid / 9, rem = bid % 9;      // 576 = 9 * 64; 5 gemm + 4 dog
    if (rem < 5) gemm_path(grp * 5 + rem, smem, out);
    else         dog_path(grp * 4 + (rem - 5), smem, base_w, scale, trans, out);
}

// ---------------------------------------------------------------------------
extern "C" void kernel_launch(void* const* d_in, const int* in_sizes, int n_in,
                              void* d_out, int out_size)
{
    const float* X        = (const float*)d_in[0];
    const float* ln_w     = (const float*)d_in[1];
    const float* ln_b     = (const float*)d_in[2];
    const float* base_w   = (const float*)d_in[3];
    const float* spline_w = (const float*)d_in[4];
    const float* scale    = (const float*)d_in[5];
    const float* trans    = (const float*)d_in[6];
    const float* grid_rbf = (const float*)d_in[7];
    const float* grid_bs  = (const float*)d_in[8];
    float* out = (float*)d_out;

    cudaFuncSetAttribute(fat_kernel, cudaFuncAttributeMaxDynamicSharedMemorySize, SMEM_BYTES);

    prep_kernel<<<PREP_BLOCKS, 256>>>(X, ln_w, ln_b, spline_w, base_w,
                                      grid_rbf, grid_bs);
    fat_kernel<<<FAT_BLOCKS, 256, SMEM_BYTES>>>(out, base_w, scale, trans);
}